// round 1
// baseline (speedup 1.0000x reference)
#include <cuda_runtime.h>
#include <cstdint>
#include <cstddef>

#define NN 20000
#define DEG 16

// ---------------- scratch (static device globals; no allocation) ----------------
__device__ unsigned char g_mask0[NN];
__device__ unsigned char g_mask1[NN];
__device__ unsigned char g_mask2[NN];
__device__ int   g_list0[4928];     // |S0| <= 4913
__device__ int   g_list1[320];      // |S1| <= 289
__device__ int   g_list2[32];       // |S2| <= 17
__device__ int   g_list3[1] = {14}; // S3
__device__ int   g_cnt[4] = {0, 0, 0, 1};  // cnt[3] fixed = 1, never written
__device__ float g_logits[NN];
__device__ float g_hN[320 * 1024];           // messages, compact-indexed
__device__ float g_h1[(size_t)NN * 512];     // h after layer 0 (node-indexed)
__device__ float g_h2[(size_t)NN * 256];     // h after layer 1
__device__ float g_h3[(size_t)NN * 128];     // h after layer 2 (only node 14 used)

// ---------------- mask build ----------------
__global__ void init_kernel() {
    int i = blockIdx.x * blockDim.x + threadIdx.x;
    if (i < NN) { g_mask0[i] = 0; g_mask1[i] = 0; g_mask2[i] = 0; }
    if (i < 3) g_cnt[i] = 0;
}

__global__ void seed_kernel(const int* __restrict__ senders) {
    int tid = threadIdx.x;
    if (tid < DEG) g_mask2[senders[14 * DEG + tid]] = 1;
    else if (tid == DEG) g_mask2[14] = 1;
}

__global__ void expand_kernel(const int* __restrict__ senders,
                              const unsigned char* __restrict__ src,
                              unsigned char* __restrict__ dst) {
    int i = blockIdx.x * blockDim.x + threadIdx.x;
    if (i >= NN) return;
    if (src[i]) {
        dst[i] = 1;
        #pragma unroll
        for (int k = 0; k < DEG; k++) dst[senders[i * DEG + k]] = 1;
    }
}

__global__ void compact_kernel(const unsigned char* __restrict__ mask,
                               int* __restrict__ list, int* __restrict__ cnt) {
    int i = blockIdx.x * blockDim.x + threadIdx.x;
    bool p = (i < NN) && mask[i];
    unsigned bal = __ballot_sync(0xffffffffu, p);
    int lane = threadIdx.x & 31;
    int base = 0;
    if (lane == 0 && bal) base = atomicAdd(cnt, __popc(bal));
    base = __shfl_sync(0xffffffffu, base, 0);
    if (p) list[base + __popc(bal & ((1u << lane) - 1u))] = i;
}

// ---------------- step 1: logits[j] = aq . relu(h[j] @ aw)  (rows from list) ----------------
// blockDim = 128, 16 rows/block, dh = CPT*128
template <int CPT>
__global__ void gemm_logits_kernel(const float* __restrict__ hin,
                                   const float* __restrict__ aw,
                                   const float* __restrict__ aq,
                                   float* __restrict__ logits,
                                   const int* __restrict__ list,
                                   const int* __restrict__ cntPtr,
                                   int din) {
    const int dh  = CPT * 128;
    const int tid = threadIdx.x;
    const int cnt = *cntPtr;
    const int row0 = blockIdx.x * 16;
    if (row0 >= cnt) return;
    const int rows = min(16, cnt - row0);

    __shared__ int   snode[16];
    __shared__ float xs[16][33];
    if (tid < 16) snode[tid] = list[row0 + (tid < rows ? tid : 0)];
    __syncthreads();

    float acc[16][CPT];
    #pragma unroll
    for (int r = 0; r < 16; r++)
        #pragma unroll
        for (int c = 0; c < CPT; c++) acc[r][c] = 0.f;

    for (int d0 = 0; d0 < din; d0 += 32) {
        #pragma unroll
        for (int k = 0; k < 4; k++) {
            int idx = tid + k * 128;
            int r = idx >> 5, dd = idx & 31;
            xs[r][dd] = hin[(size_t)snode[r] * din + d0 + dd];
        }
        __syncthreads();
        #pragma unroll 4
        for (int dd = 0; dd < 32; dd++) {
            float w[CPT];
            #pragma unroll
            for (int c = 0; c < CPT; c++) w[c] = aw[(size_t)(d0 + dd) * dh + c * 128 + tid];
            #pragma unroll
            for (int r = 0; r < 16; r++) {
                float xv = xs[r][dd];
                #pragma unroll
                for (int c = 0; c < CPT; c++) acc[r][c] = fmaf(xv, w[c], acc[r][c]);
            }
        }
        __syncthreads();
    }

    // epilogue: per-row sum_c aq[c]*relu(acc[r][c]) reduced across block
    float aqv[CPT];
    #pragma unroll
    for (int c = 0; c < CPT; c++) aqv[c] = aq[c * 128 + tid];

    __shared__ float red[4][16];
    #pragma unroll
    for (int r = 0; r < 16; r++) {
        float v = 0.f;
        #pragma unroll
        for (int c = 0; c < CPT; c++) v += aqv[c] * fmaxf(acc[r][c], 0.f);
        #pragma unroll
        for (int off = 16; off > 0; off >>= 1) v += __shfl_xor_sync(0xffffffffu, v, off);
        if ((tid & 31) == 0) red[tid >> 5][r] = v;
    }
    __syncthreads();
    if (tid < rows)
        logits[snode[tid]] = red[0][tid] + red[1][tid] + red[2][tid] + red[3][tid];
}

// ---------------- step 2: softmax over 16 neighbors + weighted message ----------------
__global__ void attn_kernel(const float* __restrict__ hin,
                            const float* __restrict__ logits,
                            const int* __restrict__ senders,
                            const int* __restrict__ list,
                            const int* __restrict__ cntPtr,
                            float* __restrict__ hN, int din) {
    int pos = blockIdx.x;
    if (pos >= *cntPtr) return;
    int node = list[pos];
    int tid = threadIdx.x;

    __shared__ int   ss[16];
    __shared__ float sw[16];
    __shared__ float sinv;
    if (tid < 32) {
        float el = -1e30f;
        int s = 0;
        if (tid < 16) { s = senders[node * DEG + tid]; el = logits[s]; ss[tid] = s; }
        float m = el;
        #pragma unroll
        for (int off = 8; off > 0; off >>= 1) m = fmaxf(m, __shfl_xor_sync(0xffffffffu, m, off));
        float w = (tid < 16) ? expf(el - m) : 0.f;
        float sum = w;
        #pragma unroll
        for (int off = 8; off > 0; off >>= 1) sum += __shfl_xor_sync(0xffffffffu, sum, off);
        if (tid < 16) sw[tid] = w;
        if (tid == 0) sinv = 1.f / sum;
    }
    __syncthreads();
    float inv = sinv;
    for (int d = tid; d < din; d += blockDim.x) {
        float m = 0.f;
        #pragma unroll
        for (int k = 0; k < 16; k++) m = fmaf(sw[k], hin[(size_t)ss[k] * din + d], m);
        hN[(size_t)pos * din + d] = m * inv;
    }
}

// ---------------- step 3: h_out = relu(concat(h_in, hN) @ lw + lb) ----------------
// blockDim = 128, 16 rows/block, col tile = CPT*128 (grid.y tiles)
template <int CPT>
__global__ void gemm_linear_kernel(const float* __restrict__ hin,
                                   const float* __restrict__ hN,
                                   const float* __restrict__ lw,
                                   const float* __restrict__ lb,
                                   float* __restrict__ hout,
                                   const int* __restrict__ list,
                                   const int* __restrict__ cntPtr,
                                   int din, int dh) {
    const int tid = threadIdx.x;
    const int cnt = *cntPtr;
    const int row0 = blockIdx.x * 16;
    if (row0 >= cnt) return;
    const int rows = min(16, cnt - row0);
    const int colBase = blockIdx.y * (128 * CPT);

    __shared__ int   snode[16];
    __shared__ float xs[16][33];
    if (tid < 16) snode[tid] = list[row0 + (tid < rows ? tid : 0)];
    __syncthreads();

    float acc[16][CPT];
    #pragma unroll
    for (int r = 0; r < 16; r++)
        #pragma unroll
        for (int c = 0; c < CPT; c++) acc[r][c] = 0.f;

    const int din2 = 2 * din;
    for (int d0 = 0; d0 < din2; d0 += 32) {
        #pragma unroll
        for (int k = 0; k < 4; k++) {
            int idx = tid + k * 128;
            int r = idx >> 5, dd = idx & 31;
            int d = d0 + dd;
            float v;
            if (d < din) v = hin[(size_t)snode[r] * din + d];
            else {
                int pr = row0 + (r < rows ? r : 0);
                v = hN[(size_t)pr * din + (d - din)];
            }
            xs[r][dd] = v;
        }
        __syncthreads();
        #pragma unroll 4
        for (int dd = 0; dd < 32; dd++) {
            float w[CPT];
            #pragma unroll
            for (int c = 0; c < CPT; c++) w[c] = lw[(size_t)(d0 + dd) * dh + colBase + c * 128 + tid];
            #pragma unroll
            for (int r = 0; r < 16; r++) {
                float xv = xs[r][dd];
                #pragma unroll
                for (int c = 0; c < CPT; c++) acc[r][c] = fmaf(xv, w[c], acc[r][c]);
            }
        }
        __syncthreads();
    }

    float bias[CPT];
    #pragma unroll
    for (int c = 0; c < CPT; c++) bias[c] = lb[colBase + c * 128 + tid];
    for (int r = 0; r < rows; r++) {
        #pragma unroll
        for (int c = 0; c < CPT; c++) {
            hout[(size_t)snode[r] * dh + colBase + c * 128 + tid] =
                fmaxf(acc[r][c] + bias[c], 0.f);
        }
    }
}

// ---------------- final: out = h3[14] @ ow + ob ----------------
__global__ void out_kernel(const float* __restrict__ ow,
                           const float* __restrict__ ob,
                           float* __restrict__ out) {
    __shared__ float hs[128];
    int tid = threadIdx.x;
    hs[tid] = g_h3[(size_t)14 * 128 + tid];
    __syncthreads();
    float acc = ob[tid];
    #pragma unroll 8
    for (int d = 0; d < 128; d++) acc = fmaf(hs[d], ow[d * 128 + tid], acc);
    out[tid] = acc;
}

// ---------------- launch ----------------
extern "C" void kernel_launch(void* const* d_in, const int* in_sizes, int n_in,
                              void* d_out, int out_size) {
    const float* X       = (const float*)d_in[0];
    const int*   senders = (const int*)d_in[1];
    const float* lw0 = (const float*)d_in[3];
    const float* lb0 = (const float*)d_in[4];
    const float* aw0 = (const float*)d_in[5];
    const float* aq0 = (const float*)d_in[6];
    const float* lw1 = (const float*)d_in[7];
    const float* lb1 = (const float*)d_in[8];
    const float* aw1 = (const float*)d_in[9];
    const float* aq1 = (const float*)d_in[10];
    const float* lw2 = (const float*)d_in[11];
    const float* lb2 = (const float*)d_in[12];
    const float* aw2 = (const float*)d_in[13];
    const float* aq2 = (const float*)d_in[14];
    const float* ow  = (const float*)d_in[15];
    const float* ob  = (const float*)d_in[16];

    // symbol addresses (host API, not stream ops — capture-safe)
    unsigned char *m0, *m1, *m2;
    int *l0, *l1, *l2, *l3, *cnt;
    float *logits, *hN, *h1, *h2, *h3;
    cudaGetSymbolAddress((void**)&m0, g_mask0);
    cudaGetSymbolAddress((void**)&m1, g_mask1);
    cudaGetSymbolAddress((void**)&m2, g_mask2);
    cudaGetSymbolAddress((void**)&l0, g_list0);
    cudaGetSymbolAddress((void**)&l1, g_list1);
    cudaGetSymbolAddress((void**)&l2, g_list2);
    cudaGetSymbolAddress((void**)&l3, g_list3);
    cudaGetSymbolAddress((void**)&cnt, g_cnt);
    cudaGetSymbolAddress((void**)&logits, g_logits);
    cudaGetSymbolAddress((void**)&hN, g_hN);
    cudaGetSymbolAddress((void**)&h1, g_h1);
    cudaGetSymbolAddress((void**)&h2, g_h2);
    cudaGetSymbolAddress((void**)&h3, g_h3);

    const int TPB = 256;
    const int NB = (NN + TPB - 1) / TPB;

    // dependency-cone construction
    init_kernel<<<NB, TPB>>>();
    seed_kernel<<<1, 32>>>(senders);
    expand_kernel<<<NB, TPB>>>(senders, m2, m1);
    expand_kernel<<<NB, TPB>>>(senders, m1, m0);
    compact_kernel<<<NB, TPB>>>(m0, l0, cnt + 0);
    compact_kernel<<<NB, TPB>>>(m1, l1, cnt + 1);
    compact_kernel<<<NB, TPB>>>(m2, l2, cnt + 2);

    // ---- layer 0: din=1024, dh=512 ----
    gemm_logits_kernel<4><<<308, 128>>>(X, aw0, aq0, logits, l0, cnt + 0, 1024);
    attn_kernel<<<289, 128>>>(X, logits, senders, l1, cnt + 1, hN, 1024);
    gemm_linear_kernel<2><<<dim3(19, 2), 128>>>(X, hN, lw0, lb0, h1, l1, cnt + 1, 1024, 512);

    // ---- layer 1: din=512, dh=256 ----
    gemm_logits_kernel<2><<<19, 128>>>(h1, aw1, aq1, logits, l1, cnt + 1, 512);
    attn_kernel<<<17, 128>>>(h1, logits, senders, l2, cnt + 2, hN, 512);
    gemm_linear_kernel<2><<<dim3(2, 1), 128>>>(h1, hN, lw1, lb1, h2, l2, cnt + 2, 512, 256);

    // ---- layer 2: din=256, dh=128 ----
    gemm_logits_kernel<1><<<2, 128>>>(h2, aw2, aq2, logits, l2, cnt + 2, 256);
    attn_kernel<<<1, 128>>>(h2, logits, senders, l3, cnt + 3, hN, 256);
    gemm_linear_kernel<1><<<dim3(1, 1), 128>>>(h2, hN, lw2, lb2, h3, l3, cnt + 3, 256, 128);

    // ---- output head ----
    out_kernel<<<1, 128>>>(ow, ob, (float*)d_out);
}

// round 2
// speedup vs baseline: 1.3530x; 1.3530x over previous
#include <cuda_runtime.h>
#include <cstdint>
#include <cstddef>

#define NN 20000
#define DEG 16

// ---------------- scratch (static device globals; no allocation) ----------------
__device__ int   g_mask0[NN];
__device__ int   g_mask1[NN];
__device__ int   g_mask2[NN];
__device__ int   g_list0[4928];     // |S0| <= 4913
__device__ int   g_list1[320];      // |S1| <= 289
__device__ int   g_list2[32];       // |S2| <= 17
__device__ int   g_list3[1] = {14}; // S3
__device__ int   g_cnt[4] = {0, 0, 0, 1};  // cnt[3] fixed = 1, never written
__device__ float g_logits[NN];
__device__ float g_hN[320 * 1024];           // messages, compact-indexed
__device__ float g_part[4 * 320 * 512];      // split-K partials
__device__ float g_h1[(size_t)NN * 512];     // h after layer 0 (node-indexed)
__device__ float g_h2[(size_t)NN * 256];     // h after layer 1
__device__ float g_h3[(size_t)NN * 128];     // h after layer 2 (only node 14 used)

// ---------------- f32x2 helpers ----------------
__device__ __forceinline__ unsigned long long pack_dup(float w) {
    unsigned long long r;
    asm("mov.b64 %0, {%1, %1};" : "=l"(r) : "r"(__float_as_uint(w)));
    return r;
}
__device__ __forceinline__ void fma2(unsigned long long& acc,
                                     unsigned long long a, unsigned long long b) {
    asm("fma.rn.f32x2 %0, %1, %2, %0;" : "+l"(acc) : "l"(a), "l"(b));
}

// ---------------- cone construction ----------------
__global__ void clear_kernel() {
    int i = blockIdx.x * blockDim.x + threadIdx.x;
    if (i < NN) { g_mask0[i] = 0; g_mask1[i] = 0; g_mask2[i] = 0; }
    if (i < 3) g_cnt[i] = 0;
}

__global__ void cone_kernel(const int* __restrict__ senders) {
    const int tid = threadIdx.x;
    const int B = blockDim.x;
    // level 2: node 14 + its senders
    if (tid < 17) {
        int s = (tid < 16) ? senders[14 * DEG + tid] : 14;
        if (atomicExch(&g_mask2[s], 1) == 0) {
            int idx = atomicAdd(&g_cnt[2], 1);
            g_list2[idx] = s;
        }
    }
    __syncthreads();
    int c2 = g_cnt[2];
    for (int t = tid; t < c2 * 17; t += B) {
        int i = t / 17, k = t - i * 17;
        int node = g_list2[i];
        int s = (k < 16) ? senders[node * DEG + k] : node;
        if (atomicExch(&g_mask1[s], 1) == 0) {
            int idx = atomicAdd(&g_cnt[1], 1);
            g_list1[idx] = s;
        }
    }
    __syncthreads();
    int c1 = g_cnt[1];
    for (int t = tid; t < c1 * 17; t += B) {
        int i = t / 17, k = t - i * 17;
        int node = g_list1[i];
        int s = (k < 16) ? senders[node * DEG + k] : node;
        if (atomicExch(&g_mask0[s], 1) == 0) {
            int idx = atomicAdd(&g_cnt[0], 1);
            g_list0[idx] = s;
        }
    }
}

// ---------------- logits: logits[j] = aq . relu(h[j] @ aw) ----------------
// 256 threads, 16 rows/block, f32x2 row-pair packing. DH = output width.
template <int DH>
__global__ __launch_bounds__(256)
void logits2_kernel(const float* __restrict__ hin,
                    const float* __restrict__ aw,
                    const float* __restrict__ aq,
                    float* __restrict__ logits,
                    const int* __restrict__ list,
                    const int* __restrict__ cntPtr,
                    int din) {
    constexpr int CPT = (DH + 255) / 256;
    const int tid = threadIdx.x;
    const int cnt = *cntPtr;
    const int row0 = blockIdx.x * 16;
    if (row0 >= cnt) return;
    const int rows = min(16, cnt - row0);

    __shared__ int snode[16];
    __shared__ float2 xs2[8][33];   // [rowpair][dd], row even -> .x, odd -> .y
    if (tid < 16) snode[tid] = list[row0 + (tid < rows ? tid : 0)];
    __syncthreads();

    unsigned long long acc[8][CPT];
    #pragma unroll
    for (int rp = 0; rp < 8; rp++)
        #pragma unroll
        for (int c = 0; c < CPT; c++) acc[rp][c] = 0ull;

    for (int d0 = 0; d0 < din; d0 += 32) {
        if (tid < 128) {
            int r = tid >> 3, q = tid & 7;
            const float4 v = *reinterpret_cast<const float4*>(
                &hin[(size_t)snode[r] * din + d0 + q * 4]);
            float2* row = xs2[r >> 1];
            int c0 = q * 4;
            if (r & 1) { row[c0].y = v.x; row[c0+1].y = v.y; row[c0+2].y = v.z; row[c0+3].y = v.w; }
            else       { row[c0].x = v.x; row[c0+1].x = v.y; row[c0+2].x = v.z; row[c0+3].x = v.w; }
        }
        __syncthreads();

        #pragma unroll 8
        for (int dd = 0; dd < 32; dd++) {
            unsigned long long w2[CPT];
            #pragma unroll
            for (int c = 0; c < CPT; c++) {
                int col = c * 256 + tid;
                float w = (col < DH) ? __ldg(&aw[(size_t)(d0 + dd) * DH + col]) : 0.f;
                w2[c] = pack_dup(w);
            }
            #pragma unroll
            for (int rp = 0; rp < 8; rp++) {
                unsigned long long x2 =
                    *reinterpret_cast<const unsigned long long*>(&xs2[rp][dd]);
                #pragma unroll
                for (int c = 0; c < CPT; c++) fma2(acc[rp][c], x2, w2[c]);
            }
        }
        __syncthreads();
    }

    // epilogue: per-row sum_c aq[c]*relu(acc), block-wide reduce
    float aqv[CPT];
    #pragma unroll
    for (int c = 0; c < CPT; c++) {
        int col = c * 256 + tid;
        aqv[c] = (col < DH) ? aq[col] : 0.f;
    }
    __shared__ float red[8][16];
    const int lane = tid & 31, wid = tid >> 5;
    #pragma unroll
    for (int r = 0; r < 16; r++) {
        int rp = r >> 1;
        float v = 0.f;
        #pragma unroll
        for (int c = 0; c < CPT; c++) {
            unsigned long long a = acc[rp][c];
            unsigned u = (r & 1) ? (unsigned)(a >> 32) : (unsigned)a;
            v += aqv[c] * fmaxf(__uint_as_float(u), 0.f);
        }
        #pragma unroll
        for (int off = 16; off > 0; off >>= 1) v += __shfl_xor_sync(0xffffffffu, v, off);
        if (lane == 0) red[wid][r] = v;
    }
    __syncthreads();
    if (tid < rows) {
        float s = 0.f;
        #pragma unroll
        for (int w = 0; w < 8; w++) s += red[w][tid];
        logits[snode[tid]] = s;
    }
}

// ---------------- softmax over 16 neighbors + weighted message ----------------
__global__ void attn_kernel(const float* __restrict__ hin,
                            const float* __restrict__ logits,
                            const int* __restrict__ senders,
                            const int* __restrict__ list,
                            const int* __restrict__ cntPtr,
                            float* __restrict__ hN, int din) {
    int pos = blockIdx.x;
    if (pos >= *cntPtr) return;
    int node = list[pos];
    int tid = threadIdx.x;

    __shared__ int   ss[16];
    __shared__ float sw[16];
    __shared__ float sinv;
    if (tid < 32) {
        float el = -1e30f;
        int s = 0;
        if (tid < 16) { s = senders[node * DEG + tid]; el = logits[s]; ss[tid] = s; }
        float m = el;
        #pragma unroll
        for (int off = 8; off > 0; off >>= 1) m = fmaxf(m, __shfl_xor_sync(0xffffffffu, m, off));
        float w = (tid < 16) ? expf(el - m) : 0.f;
        float sum = w;
        #pragma unroll
        for (int off = 8; off > 0; off >>= 1) sum += __shfl_xor_sync(0xffffffffu, sum, off);
        if (tid < 16) sw[tid] = w;
        if (tid == 0) sinv = 1.f / sum;
    }
    __syncthreads();
    float inv = sinv;
    for (int d = tid; d < din; d += blockDim.x) {
        float m = 0.f;
        #pragma unroll
        for (int k = 0; k < 16; k++) m = fmaf(sw[k], hin[(size_t)ss[k] * din + d], m);
        hN[(size_t)pos * din + d] = m * inv;
    }
}

// ---------------- linear (split-K): partial = concat(h,hN)[kchunk] @ lw[kchunk] ----------------
// 256 threads, 16 rows/block, grid.y = col tiles of 256, grid.z = K chunks of 512
__global__ __launch_bounds__(256)
void linear2_kernel(const float* __restrict__ hin,
                    const float* __restrict__ hN,
                    const float* __restrict__ lw,
                    float* __restrict__ part,
                    const int* __restrict__ list,
                    const int* __restrict__ cntPtr,
                    int din, int dh) {
    const int tid = threadIdx.x;
    const int cnt = *cntPtr;
    const int row0 = blockIdx.x * 16;
    if (row0 >= cnt) return;
    const int rows = min(16, cnt - row0);
    const int col = blockIdx.y * 256 + tid;
    const bool active = (col < dh);
    const int z = blockIdx.z;
    const int kBase = z * 512;

    __shared__ int snode[16];
    __shared__ float2 xs2[8][33];
    if (tid < 16) snode[tid] = list[row0 + (tid < rows ? tid : 0)];
    __syncthreads();

    unsigned long long acc[8];
    #pragma unroll
    for (int rp = 0; rp < 8; rp++) acc[rp] = 0ull;

    for (int d0 = kBase; d0 < kBase + 512; d0 += 32) {
        if (tid < 128) {
            int r = tid >> 3, q = tid & 7;
            int d = d0 + q * 4;
            float4 v;
            if (d < din) {
                v = *reinterpret_cast<const float4*>(&hin[(size_t)snode[r] * din + d]);
            } else {
                int pr = row0 + (r < rows ? r : 0);
                v = *reinterpret_cast<const float4*>(&hN[(size_t)pr * din + (d - din)]);
            }
            float2* row = xs2[r >> 1];
            int c0 = q * 4;
            if (r & 1) { row[c0].y = v.x; row[c0+1].y = v.y; row[c0+2].y = v.z; row[c0+3].y = v.w; }
            else       { row[c0].x = v.x; row[c0+1].x = v.y; row[c0+2].x = v.z; row[c0+3].x = v.w; }
        }
        __syncthreads();

        #pragma unroll 8
        for (int dd = 0; dd < 32; dd++) {
            float w = active ? __ldg(&lw[(size_t)(d0 + dd) * dh + col]) : 0.f;
            unsigned long long w2 = pack_dup(w);
            #pragma unroll
            for (int rp = 0; rp < 8; rp++) {
                unsigned long long x2 =
                    *reinterpret_cast<const unsigned long long*>(&xs2[rp][dd]);
                fma2(acc[rp], x2, w2);
            }
        }
        __syncthreads();
    }

    if (active) {
        #pragma unroll
        for (int rp = 0; rp < 8; rp++) {
            int rA = 2 * rp, rB = 2 * rp + 1;
            float lo = __uint_as_float((unsigned)acc[rp]);
            float hi = __uint_as_float((unsigned)(acc[rp] >> 32));
            if (rA < rows) part[((size_t)z * 320 + row0 + rA) * 512 + col] = lo;
            if (rB < rows) part[((size_t)z * 320 + row0 + rB) * 512 + col] = hi;
        }
    }
}

__global__ void linear_reduce_kernel(const float* __restrict__ part,
                                     const float* __restrict__ lb,
                                     float* __restrict__ hout,
                                     const int* __restrict__ list,
                                     const int* __restrict__ cntPtr,
                                     int dh, int nz) {
    int pos = blockIdx.x;
    if (pos >= *cntPtr) return;
    int node = list[pos];
    for (int col = threadIdx.x; col < dh; col += blockDim.x) {
        float s = lb[col];
        for (int z = 0; z < nz; z++)
            s += part[((size_t)z * 320 + pos) * 512 + col];
        hout[(size_t)node * dh + col] = fmaxf(s, 0.f);
    }
}

// ---------------- final: out = h3[14] @ ow + ob ----------------
__global__ void out_kernel(const float* __restrict__ ow,
                           const float* __restrict__ ob,
                           float* __restrict__ out) {
    __shared__ float hs[128];
    int tid = threadIdx.x;
    hs[tid] = g_h3[(size_t)14 * 128 + tid];
    __syncthreads();
    float acc = ob[tid];
    #pragma unroll 8
    for (int d = 0; d < 128; d++) acc = fmaf(hs[d], ow[d * 128 + tid], acc);
    out[tid] = acc;
}

// ---------------- launch ----------------
extern "C" void kernel_launch(void* const* d_in, const int* in_sizes, int n_in,
                              void* d_out, int out_size) {
    const float* X       = (const float*)d_in[0];
    const int*   senders = (const int*)d_in[1];
    const float* lw0 = (const float*)d_in[3];
    const float* lb0 = (const float*)d_in[4];
    const float* aw0 = (const float*)d_in[5];
    const float* aq0 = (const float*)d_in[6];
    const float* lw1 = (const float*)d_in[7];
    const float* lb1 = (const float*)d_in[8];
    const float* aw1 = (const float*)d_in[9];
    const float* aq1 = (const float*)d_in[10];
    const float* lw2 = (const float*)d_in[11];
    const float* lb2 = (const float*)d_in[12];
    const float* aw2 = (const float*)d_in[13];
    const float* aq2 = (const float*)d_in[14];
    const float* ow  = (const float*)d_in[15];
    const float* ob  = (const float*)d_in[16];

    int *l0, *l1, *l2, *l3, *cnt;
    float *logits, *hN, *part, *h1, *h2, *h3;
    cudaGetSymbolAddress((void**)&l0, g_list0);
    cudaGetSymbolAddress((void**)&l1, g_list1);
    cudaGetSymbolAddress((void**)&l2, g_list2);
    cudaGetSymbolAddress((void**)&l3, g_list3);
    cudaGetSymbolAddress((void**)&cnt, g_cnt);
    cudaGetSymbolAddress((void**)&logits, g_logits);
    cudaGetSymbolAddress((void**)&hN, g_hN);
    cudaGetSymbolAddress((void**)&part, g_part);
    cudaGetSymbolAddress((void**)&h1, g_h1);
    cudaGetSymbolAddress((void**)&h2, g_h2);
    cudaGetSymbolAddress((void**)&h3, g_h3);

    // dependency-cone construction (2 launches)
    clear_kernel<<<(NN + 255) / 256, 256>>>();
    cone_kernel<<<1, 1024>>>(senders);

    // ---- layer 0: din=1024, dh=512 ----
    logits2_kernel<512><<<308, 256>>>(X, aw0, aq0, logits, l0, cnt + 0, 1024);
    attn_kernel<<<289, 256>>>(X, logits, senders, l1, cnt + 1, hN, 1024);
    linear2_kernel<<<dim3(19, 2, 4), 256>>>(X, hN, lw0, part, l1, cnt + 1, 1024, 512);
    linear_reduce_kernel<<<289, 256>>>(part, lb0, h1, l1, cnt + 1, 512, 4);

    // ---- layer 1: din=512, dh=256 ----
    logits2_kernel<256><<<19, 256>>>(h1, aw1, aq1, logits, l1, cnt + 1, 512);
    attn_kernel<<<17, 256>>>(h1, logits, senders, l2, cnt + 2, hN, 512);
    linear2_kernel<<<dim3(2, 1, 2), 256>>>(h1, hN, lw1, part, l2, cnt + 2, 512, 256);
    linear_reduce_kernel<<<17, 256>>>(part, lb1, h2, l2, cnt + 2, 256, 2);

    // ---- layer 2: din=256, dh=128 ----
    logits2_kernel<128><<<2, 256>>>(h2, aw2, aq2, logits, l2, cnt + 2, 256);
    attn_kernel<<<1, 256>>>(h2, logits, senders, l3, cnt + 3, hN, 256);
    linear2_kernel<<<dim3(1, 1, 1), 256>>>(h2, hN, lw2, part, l3, cnt + 3, 256, 128);
    linear_reduce_kernel<<<1, 128>>>(part, lb2, h3, l3, cnt + 3, 128, 1);

    // ---- output head ----
    out_kernel<<<1, 128>>>(ow, ob, (float*)d_out);
}

// round 3
// speedup vs baseline: 2.4807x; 1.8335x over previous
#include <cuda_runtime.h>
#include <cstdint>
#include <cstddef>

#define NN 20000
#define DEG 16

// ---------------- scratch (static device globals; no allocation) ----------------
__device__ int   g_mask0[NN];
__device__ int   g_mask1[NN];
__device__ int   g_mask2[NN];
__device__ int   g_list0[4928];
__device__ int   g_list1[320];
__device__ int   g_list2[32];
__device__ int   g_list3[1] = {14};
__device__ int   g_cnt[4] = {0, 0, 0, 1};
__device__ float g_logits[NN];
__device__ float g_hN[320 * 1024];
__device__ float g_part[8 * 320 * 512];
__device__ float g_h1[(size_t)NN * 512];
__device__ float g_h2[(size_t)NN * 256];
__device__ float g_h3[(size_t)NN * 128];

// ---------------- f32x2 helpers ----------------
__device__ __forceinline__ unsigned long long pack_dup(float w) {
    unsigned long long r;
    asm("mov.b64 %0, {%1, %1};" : "=l"(r) : "r"(__float_as_uint(w)));
    return r;
}
__device__ __forceinline__ void fma2(unsigned long long& acc,
                                     unsigned long long a, unsigned long long b) {
    asm("fma.rn.f32x2 %0, %1, %2, %0;" : "+l"(acc) : "l"(a), "l"(b));
}

// ---------------- cone construction ----------------
__global__ void clear_kernel() {
    int i = blockIdx.x * blockDim.x + threadIdx.x;
    if (i < NN) { g_mask0[i] = 0; g_mask1[i] = 0; g_mask2[i] = 0; }
    if (i < 3) g_cnt[i] = 0;
}

__global__ void cone_kernel(const int* __restrict__ senders) {
    const int tid = threadIdx.x;
    const int B = blockDim.x;
    if (tid < 17) {
        int s = (tid < 16) ? senders[14 * DEG + tid] : 14;
        if (atomicExch(&g_mask2[s], 1) == 0) {
            int idx = atomicAdd(&g_cnt[2], 1);
            g_list2[idx] = s;
        }
    }
    __syncthreads();
    int c2 = g_cnt[2];
    for (int t = tid; t < c2 * 17; t += B) {
        int i = t / 17, k = t - i * 17;
        int node = g_list2[i];
        int s = (k < 16) ? senders[node * DEG + k] : node;
        if (atomicExch(&g_mask1[s], 1) == 0) {
            int idx = atomicAdd(&g_cnt[1], 1);
            g_list1[idx] = s;
        }
    }
    __syncthreads();
    int c1 = g_cnt[1];
    for (int t = tid; t < c1 * 17; t += B) {
        int i = t / 17, k = t - i * 17;
        int node = g_list1[i];
        int s = (k < 16) ? senders[node * DEG + k] : node;
        if (atomicExch(&g_mask0[s], 1) == 0) {
            int idx = atomicAdd(&g_cnt[0], 1);
            g_list0[idx] = s;
        }
    }
}

// ---------------- GEMM cores ----------------
// ROWS rows/block (16 or 32), 256 threads, CPT columns/thread (1 or 2, consecutive).
// Rows packed 4-per-ulonglong2 in smem -> LDS.128 broadcast; f32x2 row-pair FMA.

template <int CPT>
__device__ __forceinline__ void loadW(const float* __restrict__ w, size_t d,
                                      int dh, int col0, bool wact, float* out) {
    if (CPT == 2) {
        float2 t = wact ? *reinterpret_cast<const float2*>(&w[d * dh + col0])
                        : make_float2(0.f, 0.f);
        out[0] = t.x; out[1] = t.y;
    } else {
        out[0] = wact ? w[d * dh + col0] : 0.f;
    }
}

template <int ROWS, int CPT>
__global__ __launch_bounds__(256)
void gemm_logits_kernel(const float* __restrict__ hin,
                        const float* __restrict__ aw,
                        const float* __restrict__ aq,
                        float* __restrict__ logits,
                        const int* __restrict__ list,
                        const int* __restrict__ cntPtr,
                        int din, int dh) {
    const int tid = threadIdx.x;
    const int cnt = *cntPtr;
    const int row0 = blockIdx.x * ROWS;
    if (row0 >= cnt) return;
    const int rows = min(ROWS, cnt - row0);

    __shared__ int snode[ROWS];
    __shared__ ulonglong2 xs[ROWS / 4][33];
    if (tid < ROWS) snode[tid] = list[row0 + (tid < rows ? tid : 0)];
    __syncthreads();

    const int r = tid >> 3, q = tid & 7;
    const bool ract = (r < ROWS);
    const int col0 = CPT * tid;
    const bool wact = (col0 + CPT - 1 < dh);

    unsigned long long acc[ROWS / 2][CPT];
    #pragma unroll
    for (int rp = 0; rp < ROWS / 2; rp++)
        #pragma unroll
        for (int c = 0; c < CPT; c++) acc[rp][c] = 0ull;

    float4 v = make_float4(0.f, 0.f, 0.f, 0.f);
    size_t rowBase = 0;
    if (ract) {
        rowBase = (size_t)snode[r] * din;
        v = *reinterpret_cast<const float4*>(&hin[rowBase + q * 4]);
    }

    for (int d0 = 0; d0 < din; d0 += 32) {
        if (ract) {
            float* dst = (float*)&xs[r >> 2][q * 4];
            dst[0 * 4 + (r & 3)] = v.x;
            dst[1 * 4 + (r & 3)] = v.y;
            dst[2 * 4 + (r & 3)] = v.z;
            dst[3 * 4 + (r & 3)] = v.w;
        }
        __syncthreads();
        if (ract && d0 + 32 < din)
            v = *reinterpret_cast<const float4*>(&hin[rowBase + d0 + 32 + q * 4]);

        float wr[4][CPT];
        #pragma unroll
        for (int p = 0; p < 4; p++)
            loadW<CPT>(aw, (size_t)(d0 + p), dh, col0, wact, wr[p]);

        #pragma unroll
        for (int dd = 0; dd < 32; dd++) {
            unsigned long long w2[CPT];
            #pragma unroll
            for (int c = 0; c < CPT; c++) w2[c] = pack_dup(wr[dd & 3][c]);
            if (dd + 4 < 32)
                loadW<CPT>(aw, (size_t)(d0 + dd + 4), dh, col0, wact, wr[dd & 3]);
            #pragma unroll
            for (int g = 0; g < ROWS / 4; g++) {
                ulonglong2 p = xs[g][dd];
                #pragma unroll
                for (int c = 0; c < CPT; c++) {
                    fma2(acc[2 * g + 0][c], p.x, w2[c]);
                    fma2(acc[2 * g + 1][c], p.y, w2[c]);
                }
            }
        }
        __syncthreads();
    }

    // epilogue: logits[row] = sum_col aq[col] * relu(acc)
    float aqv[CPT];
    #pragma unroll
    for (int c = 0; c < CPT; c++)
        aqv[c] = (col0 + c < dh) ? aq[col0 + c] : 0.f;

    __shared__ float red[8][ROWS];
    const int lane = tid & 31, wid = tid >> 5;
    #pragma unroll
    for (int rr = 0; rr < ROWS; rr++) {
        int rp = rr >> 1;
        float s = 0.f;
        #pragma unroll
        for (int c = 0; c < CPT; c++) {
            unsigned long long a = acc[rp][c];
            unsigned u = (rr & 1) ? (unsigned)(a >> 32) : (unsigned)a;
            s += aqv[c] * fmaxf(__uint_as_float(u), 0.f);
        }
        #pragma unroll
        for (int off = 16; off > 0; off >>= 1)
            s += __shfl_xor_sync(0xffffffffu, s, off);
        if (lane == 0) red[wid][rr] = s;
    }
    __syncthreads();
    if (tid < rows) {
        float s = 0.f;
        #pragma unroll
        for (int w = 0; w < 8; w++) s += red[w][tid];
        logits[snode[tid]] = s;
    }
}

template <int ROWS, int CPT>
__global__ __launch_bounds__(256)
void gemm_linear_kernel(const float* __restrict__ hin,
                        const float* __restrict__ hN,
                        const float* __restrict__ lw,
                        float* __restrict__ part,
                        const int* __restrict__ list,
                        const int* __restrict__ cntPtr,
                        int din, int dh, int kch) {
    const int tid = threadIdx.x;
    const int cnt = *cntPtr;
    const int row0 = blockIdx.x * ROWS;
    if (row0 >= cnt) return;
    const int rows = min(ROWS, cnt - row0);
    const int z = blockIdx.z;
    const int k0 = z * kch, k1 = k0 + kch;

    __shared__ int snode[ROWS];
    __shared__ ulonglong2 xs[ROWS / 4][33];
    if (tid < ROWS) snode[tid] = list[row0 + (tid < rows ? tid : 0)];
    __syncthreads();

    const int r = tid >> 3, q = tid & 7;
    const bool ract = (r < ROWS);
    const int col0 = CPT * tid;
    const bool wact = (col0 + CPT - 1 < dh);

    unsigned long long acc[ROWS / 2][CPT];
    #pragma unroll
    for (int rp = 0; rp < ROWS / 2; rp++)
        #pragma unroll
        for (int c = 0; c < CPT; c++) acc[rp][c] = 0ull;

    size_t rowBase = 0, hnBase = 0;
    if (ract) {
        rowBase = (size_t)snode[r] * din;
        hnBase = (size_t)(row0 + (r < rows ? r : 0)) * din;
    }
    auto loadX = [&](int d) -> float4 {
        if (d < din) return *reinterpret_cast<const float4*>(&hin[rowBase + d]);
        return *reinterpret_cast<const float4*>(&hN[hnBase + (d - din)]);
    };

    float4 v = make_float4(0.f, 0.f, 0.f, 0.f);
    if (ract) v = loadX(k0 + q * 4);

    for (int d0 = k0; d0 < k1; d0 += 32) {
        if (ract) {
            float* dst = (float*)&xs[r >> 2][q * 4];
            dst[0 * 4 + (r & 3)] = v.x;
            dst[1 * 4 + (r & 3)] = v.y;
            dst[2 * 4 + (r & 3)] = v.z;
            dst[3 * 4 + (r & 3)] = v.w;
        }
        __syncthreads();
        if (ract && d0 + 32 < k1) v = loadX(d0 + 32 + q * 4);

        float wr[4][CPT];
        #pragma unroll
        for (int p = 0; p < 4; p++)
            loadW<CPT>(lw, (size_t)(d0 + p), dh, col0, wact, wr[p]);

        #pragma unroll
        for (int dd = 0; dd < 32; dd++) {
            unsigned long long w2[CPT];
            #pragma unroll
            for (int c = 0; c < CPT; c++) w2[c] = pack_dup(wr[dd & 3][c]);
            if (dd + 4 < 32)
                loadW<CPT>(lw, (size_t)(d0 + dd + 4), dh, col0, wact, wr[dd & 3]);
            #pragma unroll
            for (int g = 0; g < ROWS / 4; g++) {
                ulonglong2 p = xs[g][dd];
                #pragma unroll
                for (int c = 0; c < CPT; c++) {
                    fma2(acc[2 * g + 0][c], p.x, w2[c]);
                    fma2(acc[2 * g + 1][c], p.y, w2[c]);
                }
            }
        }
        __syncthreads();
    }

    if (wact) {
        #pragma unroll
        for (int rp = 0; rp < ROWS / 2; rp++) {
            int rA = 2 * rp, rB = 2 * rp + 1;
            #pragma unroll
            for (int c = 0; c < CPT; c++) {
                float lo = __uint_as_float((unsigned)acc[rp][c]);
                float hi = __uint_as_float((unsigned)(acc[rp][c] >> 32));
                if (rA < rows) part[((size_t)z * 320 + row0 + rA) * 512 + col0 + c] = lo;
                if (rB < rows) part[((size_t)z * 320 + row0 + rB) * 512 + col0 + c] = hi;
            }
        }
    }
}

__global__ void linear_reduce_kernel(const float* __restrict__ part,
                                     const float* __restrict__ lb,
                                     float* __restrict__ hout,
                                     const int* __restrict__ list,
                                     const int* __restrict__ cntPtr,
                                     int dh, int nz) {
    int pos = blockIdx.x;
    if (pos >= *cntPtr) return;
    int node = list[pos];
    for (int col = threadIdx.x; col < dh; col += blockDim.x) {
        float s = lb[col];
        for (int z = 0; z < nz; z++)
            s += part[((size_t)z * 320 + pos) * 512 + col];
        hout[(size_t)node * dh + col] = fmaxf(s, 0.f);
    }
}

// ---------------- softmax over 16 neighbors + weighted message (float4) ----------------
__global__ void attn_kernel(const float* __restrict__ hin,
                            const float* __restrict__ logits,
                            const int* __restrict__ senders,
                            const int* __restrict__ list,
                            const int* __restrict__ cntPtr,
                            float* __restrict__ hN, int din) {
    int pos = blockIdx.x;
    if (pos >= *cntPtr) return;
    int node = list[pos];
    int tid = threadIdx.x;

    __shared__ int   ss[16];
    __shared__ float sw[16];
    __shared__ float sinv;
    if (tid < 32) {
        float el = -1e30f;
        int s = 0;
        if (tid < 16) { s = senders[node * DEG + tid]; el = logits[s]; ss[tid] = s; }
        float m = el;
        #pragma unroll
        for (int off = 8; off > 0; off >>= 1) m = fmaxf(m, __shfl_xor_sync(0xffffffffu, m, off));
        float w = (tid < 16) ? expf(el - m) : 0.f;
        float sum = w;
        #pragma unroll
        for (int off = 8; off > 0; off >>= 1) sum += __shfl_xor_sync(0xffffffffu, sum, off);
        if (tid < 16) sw[tid] = w;
        if (tid == 0) sinv = 1.f / sum;
    }
    __syncthreads();
    float inv = sinv;
    int nd4 = din >> 2;
    for (int d4 = tid; d4 < nd4; d4 += blockDim.x) {
        float4 m = make_float4(0.f, 0.f, 0.f, 0.f);
        #pragma unroll
        for (int k = 0; k < 16; k++) {
            float4 x = *reinterpret_cast<const float4*>(&hin[(size_t)ss[k] * din + d4 * 4]);
            float wk = sw[k];
            m.x = fmaf(wk, x.x, m.x);
            m.y = fmaf(wk, x.y, m.y);
            m.z = fmaf(wk, x.z, m.z);
            m.w = fmaf(wk, x.w, m.w);
        }
        m.x *= inv; m.y *= inv; m.z *= inv; m.w *= inv;
        *reinterpret_cast<float4*>(&hN[(size_t)pos * din + d4 * 4]) = m;
    }
}

// ---------------- final: out = h3[14] @ ow + ob ----------------
__global__ void out_kernel(const float* __restrict__ ow,
                           const float* __restrict__ ob,
                           float* __restrict__ out) {
    __shared__ float hs[128];
    int tid = threadIdx.x;
    hs[tid] = g_h3[(size_t)14 * 128 + tid];
    __syncthreads();
    float acc = ob[tid];
    #pragma unroll 8
    for (int d = 0; d < 128; d++) acc = fmaf(hs[d], ow[d * 128 + tid], acc);
    out[tid] = acc;
}

// ---------------- launch ----------------
extern "C" void kernel_launch(void* const* d_in, const int* in_sizes, int n_in,
                              void* d_out, int out_size) {
    const float* X       = (const float*)d_in[0];
    const int*   senders = (const int*)d_in[1];
    const float* lw0 = (const float*)d_in[3];
    const float* lb0 = (const float*)d_in[4];
    const float* aw0 = (const float*)d_in[5];
    const float* aq0 = (const float*)d_in[6];
    const float* lw1 = (const float*)d_in[7];
    const float* lb1 = (const float*)d_in[8];
    const float* aw1 = (const float*)d_in[9];
    const float* aq1 = (const float*)d_in[10];
    const float* lw2 = (const float*)d_in[11];
    const float* lb2 = (const float*)d_in[12];
    const float* aw2 = (const float*)d_in[13];
    const float* aq2 = (const float*)d_in[14];
    const float* ow  = (const float*)d_in[15];
    const float* ob  = (const float*)d_in[16];

    int *l0, *l1, *l2, *l3, *cnt;
    float *logits, *hN, *part, *h1, *h2, *h3;
    cudaGetSymbolAddress((void**)&l0, g_list0);
    cudaGetSymbolAddress((void**)&l1, g_list1);
    cudaGetSymbolAddress((void**)&l2, g_list2);
    cudaGetSymbolAddress((void**)&l3, g_list3);
    cudaGetSymbolAddress((void**)&cnt, g_cnt);
    cudaGetSymbolAddress((void**)&logits, g_logits);
    cudaGetSymbolAddress((void**)&hN, g_hN);
    cudaGetSymbolAddress((void**)&part, g_part);
    cudaGetSymbolAddress((void**)&h1, g_h1);
    cudaGetSymbolAddress((void**)&h2, g_h2);
    cudaGetSymbolAddress((void**)&h3, g_h3);

    clear_kernel<<<(NN + 255) / 256, 256>>>();
    cone_kernel<<<1, 1024>>>(senders);

    // ---- layer 0: din=1024, dh=512 ----
    gemm_logits_kernel<32, 2><<<154, 256>>>(X, aw0, aq0, logits, l0, cnt + 0, 1024, 512);
    attn_kernel<<<289, 256>>>(X, logits, senders, l1, cnt + 1, hN, 1024);
    gemm_linear_kernel<32, 2><<<dim3(10, 1, 8), 256>>>(X, hN, lw0, part, l1, cnt + 1, 1024, 512, 256);
    linear_reduce_kernel<<<289, 256>>>(part, lb0, h1, l1, cnt + 1, 512, 8);

    // ---- layer 1: din=512, dh=256 ----
    gemm_logits_kernel<16, 1><<<19, 256>>>(h1, aw1, aq1, logits, l1, cnt + 1, 512, 256);
    attn_kernel<<<17, 256>>>(h1, logits, senders, l2, cnt + 2, hN, 512);
    gemm_linear_kernel<16, 1><<<dim3(2, 1, 4), 256>>>(h1, hN, lw1, part, l2, cnt + 2, 512, 256, 256);
    linear_reduce_kernel<<<17, 256>>>(part, lb1, h2, l2, cnt + 2, 256, 4);

    // ---- layer 2: din=256, dh=128 ----
    gemm_logits_kernel<16, 1><<<2, 256>>>(h2, aw2, aq2, logits, l2, cnt + 2, 256, 128);
    attn_kernel<<<1, 256>>>(h2, logits, senders, l3, cnt + 3, hN, 256);
    gemm_linear_kernel<16, 1><<<dim3(1, 1, 2), 256>>>(h2, hN, lw2, part, l3, cnt + 3, 256, 128, 256);
    linear_reduce_kernel<<<1, 128>>>(part, lb2, h3, l3, cnt + 3, 128, 2);

    out_kernel<<<1, 128>>>(ow, ob, (float*)d_out);
}

// round 6
// speedup vs baseline: 3.7261x; 1.5021x over previous
#include <cuda_runtime.h>
#include <cstdint>
#include <cstddef>

#define NN 20000
#define DEG 16

// ---------------- scratch (static device globals; no allocation) ----------------
__device__ int   g_mask0[NN];
__device__ int   g_mask1[NN];
__device__ int   g_mask2[NN];
__device__ int   g_list0[4928];
__device__ int   g_list1[320];
__device__ int   g_list2[32];
__device__ int   g_list3[1] = {14};
__device__ int   g_cnt[4] = {0, 0, 0, 1};
__device__ float g_logits[NN];
__device__ float g_hN[320 * 1024];
__device__ float g_part[8 * 320 * 512];        // SIMT split-K partials (small layers)
__device__ float g_lpart[4 * 4992];            // logits0 per-Ntile partials
__device__ float g_partT[8 * 3 * 128 * 512];   // linear0 split-K partials
__device__ float g_wt0[512 * 1024];            // aw0 transposed [dh][din]
__device__ float g_wtL[512 * 2048];            // lw0 transposed [dh][2*din]
__device__ float g_h1[(size_t)NN * 512];
__device__ float g_h2[(size_t)NN * 256];
__device__ float g_h3[(size_t)NN * 128];

// ---------------- helpers ----------------
__device__ __forceinline__ uint32_t f2tf32(float f) {
    uint32_t r;
    asm("cvt.rna.tf32.f32 %0, %1;" : "=r"(r) : "f"(f));
    return r;
}
__device__ __forceinline__ void mma16x8x8(float* d, const uint32_t* a, const uint32_t* b) {
    asm volatile(
        "mma.sync.aligned.m16n8k8.row.col.f32.tf32.tf32.f32 "
        "{%0,%1,%2,%3}, {%4,%5,%6,%7}, {%8,%9}, {%0,%1,%2,%3};"
        : "+f"(d[0]), "+f"(d[1]), "+f"(d[2]), "+f"(d[3])
        : "r"(a[0]), "r"(a[1]), "r"(a[2]), "r"(a[3]), "r"(b[0]), "r"(b[1]));
}
__device__ __forceinline__ unsigned long long pack_dup(float w) {
    unsigned long long r;
    asm("mov.b64 %0, {%1, %1};" : "=l"(r) : "r"(__float_as_uint(w)));
    return r;
}
__device__ __forceinline__ void fma2(unsigned long long& acc,
                                     unsigned long long a, unsigned long long b) {
    asm("fma.rn.f32x2 %0, %1, %2, %0;" : "+l"(acc) : "l"(a), "l"(b));
}

// ---------------- cone construction ----------------
__global__ void clear_kernel() {
    int i = blockIdx.x * blockDim.x + threadIdx.x;
    if (i < NN) { g_mask0[i] = 0; g_mask1[i] = 0; g_mask2[i] = 0; }
    if (i < 3) g_cnt[i] = 0;
}

__global__ void cone_kernel(const int* __restrict__ senders) {
    const int tid = threadIdx.x;
    const int B = blockDim.x;
    if (tid < 17) {
        int s = (tid < 16) ? senders[14 * DEG + tid] : 14;
        if (atomicExch(&g_mask2[s], 1) == 0) g_list2[atomicAdd(&g_cnt[2], 1)] = s;
    }
    __syncthreads();
    int c2 = g_cnt[2];
    for (int t = tid; t < c2 * 17; t += B) {
        int i = t / 17, k = t - i * 17;
        int node = g_list2[i];
        int s = (k < 16) ? senders[node * DEG + k] : node;
        if (atomicExch(&g_mask1[s], 1) == 0) g_list1[atomicAdd(&g_cnt[1], 1)] = s;
    }
    __syncthreads();
    int c1 = g_cnt[1];
    for (int t = tid; t < c1 * 17; t += B) {
        int i = t / 17, k = t - i * 17;
        int node = g_list1[i];
        int s = (k < 16) ? senders[node * DEG + k] : node;
        if (atomicExch(&g_mask0[s], 1) == 0) g_list0[atomicAdd(&g_cnt[0], 1)] = s;
    }
}

// ---------------- weight transpose: dst[n][k] = src[k][n] ----------------
__global__ void transpose_kernel(const float* __restrict__ src, float* __restrict__ dst,
                                 int K, int N) {
    __shared__ float t[32][33];
    int k0 = blockIdx.x * 32, n0 = blockIdx.y * 32;
    int x = threadIdx.x, y = threadIdx.y;
    #pragma unroll
    for (int j = 0; j < 32; j += 8)
        if (k0 + y + j < K && n0 + x < N)
            t[y + j][x] = src[(size_t)(k0 + y + j) * N + n0 + x];
    __syncthreads();
    #pragma unroll
    for (int j = 0; j < 32; j += 8)
        if (n0 + y + j < N && k0 + x < K)
            dst[(size_t)(n0 + y + j) * K + k0 + x] = t[x][y + j];
}

// ---------------- mma.sync tf32 GEMM ----------------
// Tile: M=128, N=128, K-chunk=32. 256 threads = 8 warps, warp tile 32x64.
// MODE 0 (logits0): A = gather(X, list), B = wt0; epilogue -> aq.relu partial
//                   per N-tile into lpart[ntile*4992 + m0+row].
// MODE 1 (linear0): A = concat(X[list], hN), B = wtL; raw D partials
//                   into partT[((z*3+bx)*128+r)*512 + n0+c].
#define ASTR 36

template <int MODE>
__global__ __launch_bounds__(256, 1)
void mma_gemm_kernel(const float* __restrict__ X,
                     const float* __restrict__ hN,
                     const float* __restrict__ wt,
                     const float* __restrict__ aq,
                     float* __restrict__ outBuf,
                     const int* __restrict__ list,
                     const int* __restrict__ cntPtr,
                     int Ktot, int kPerSplit) {
    __shared__ uint32_t As[128 * ASTR];
    __shared__ uint32_t Bs[128 * ASTR];
    __shared__ int snode[128];
    __shared__ float sred[128];
    __shared__ float saq[128];

    const int tid = threadIdx.x;
    const int w = tid >> 5, lane = tid & 31;
    const int g = lane >> 2, t4 = lane & 3;
    const int wm = w >> 1, wn = w & 1;
    const int cnt = *cntPtr;
    const int m0 = blockIdx.x * 128;
    if (m0 >= cnt) return;
    const int n0 = blockIdx.y * 128;
    const int kBase = blockIdx.z * kPerSplit;
    const int nch = kPerSplit / 32;

    if (tid < 128) {
        int p = m0 + tid; if (p >= cnt) p = cnt - 1;
        snode[tid] = list[p];
        if (MODE == 0) saq[tid] = aq[n0 + tid];
    }
    __syncthreads();

    float acc[2][8][4];
    #pragma unroll
    for (int mf = 0; mf < 2; mf++)
        #pragma unroll
        for (int nf = 0; nf < 8; nf++)
            #pragma unroll
            for (int e = 0; e < 4; e++) acc[mf][nf][e] = 0.f;

    // per-thread staging: 4 float4 of A + 4 of B per chunk
    float4 ra[4], rb[4];
    auto loadChunk = [&](int c) {
        const int k0 = kBase + c * 32;
        #pragma unroll
        for (int j = 0; j < 4; j++) {
            int i = j * 256 + tid;
            int row = i >> 3, col = (i & 7) * 4;
            const float* srcA;
            if (MODE == 0) {
                srcA = X + (size_t)snode[row] * 1024 + k0 + col;
            } else {
                int d = k0 + col;
                if (d < 1024) srcA = X + (size_t)snode[row] * 1024 + d;
                else {
                    int p = m0 + row; if (p >= cnt) p = cnt - 1;
                    srcA = hN + (size_t)p * 1024 + (d - 1024);
                }
            }
            ra[j] = *reinterpret_cast<const float4*>(srcA);
            rb[j] = *reinterpret_cast<const float4*>(
                wt + (size_t)(n0 + row) * Ktot + k0 + col);
        }
    };
    auto stageChunk = [&]() {
        #pragma unroll
        for (int j = 0; j < 4; j++) {
            int i = j * 256 + tid;
            int row = i >> 3, col = (i & 7) * 4;
            uint4 va = make_uint4(f2tf32(ra[j].x), f2tf32(ra[j].y),
                                  f2tf32(ra[j].z), f2tf32(ra[j].w));
            uint4 vb = make_uint4(f2tf32(rb[j].x), f2tf32(rb[j].y),
                                  f2tf32(rb[j].z), f2tf32(rb[j].w));
            *reinterpret_cast<uint4*>(&As[row * ASTR + col]) = va;
            *reinterpret_cast<uint4*>(&Bs[row * ASTR + col]) = vb;
        }
    };

    loadChunk(0);
    for (int c = 0; c < nch; c++) {
        stageChunk();
        __syncthreads();
        if (c + 1 < nch) loadChunk(c + 1);

        #pragma unroll
        for (int ks = 0; ks < 4; ks++) {
            const int k0 = ks * 8;
            uint32_t af[2][4];
            #pragma unroll
            for (int mf = 0; mf < 2; mf++) {
                int r = wm * 32 + mf * 16 + g;
                af[mf][0] = As[r * ASTR + k0 + t4];
                af[mf][1] = As[(r + 8) * ASTR + k0 + t4];
                af[mf][2] = As[r * ASTR + k0 + t4 + 4];
                af[mf][3] = As[(r + 8) * ASTR + k0 + t4 + 4];
            }
            #pragma unroll
            for (int nf = 0; nf < 8; nf++) {
                int cN = wn * 64 + nf * 8 + g;
                uint32_t bf[2];
                bf[0] = Bs[cN * ASTR + k0 + t4];
                bf[1] = Bs[cN * ASTR + k0 + t4 + 4];
                mma16x8x8(acc[0][nf], af[0], bf);
                mma16x8x8(acc[1][nf], af[1], bf);
            }
        }
        __syncthreads();
    }

    if (MODE == 0) {
        // s[mf][half]: per-thread partial over this warp's 64 cols
        float s[2][2] = {{0.f, 0.f}, {0.f, 0.f}};
        #pragma unroll
        for (int mf = 0; mf < 2; mf++)
            #pragma unroll
            for (int nf = 0; nf < 8; nf++) {
                int c0 = wn * 64 + nf * 8 + t4 * 2;
                float a0 = saq[c0], a1 = saq[c0 + 1];
                s[mf][0] += a0 * fmaxf(acc[mf][nf][0], 0.f) + a1 * fmaxf(acc[mf][nf][1], 0.f);
                s[mf][1] += a0 * fmaxf(acc[mf][nf][2], 0.f) + a1 * fmaxf(acc[mf][nf][3], 0.f);
            }
        // reduce across the 4 lanes of each quad (same row)
        #pragma unroll
        for (int mf = 0; mf < 2; mf++)
            #pragma unroll
            for (int h = 0; h < 2; h++) {
                s[mf][h] += __shfl_xor_sync(0xffffffffu, s[mf][h], 1);
                s[mf][h] += __shfl_xor_sync(0xffffffffu, s[mf][h], 2);
            }
        if (wn == 0) {
            if (t4 == 0) {
                #pragma unroll
                for (int mf = 0; mf < 2; mf++) {
                    sred[wm * 32 + mf * 16 + g] = s[mf][0];
                    sred[wm * 32 + mf * 16 + g + 8] = s[mf][1];
                }
            }
        }
        __syncthreads();
        if (wn == 1 && t4 == 0) {
            #pragma unroll
            for (int mf = 0; mf < 2; mf++) {
                sred[wm * 32 + mf * 16 + g] += s[mf][0];
                sred[wm * 32 + mf * 16 + g + 8] += s[mf][1];
            }
        }
        __syncthreads();
        if (tid < 128)
            outBuf[blockIdx.y * 4992 + m0 + tid] = sred[tid];
    } else {
        const int bx = blockIdx.x, z = blockIdx.z;
        #pragma unroll
        for (int mf = 0; mf < 2; mf++) {
            int r0 = wm * 32 + mf * 16 + g;
            #pragma unroll
            for (int nf = 0; nf < 8; nf++) {
                int c0 = n0 + wn * 64 + nf * 8 + t4 * 2;
                size_t b0 = ((size_t)(z * 3 + bx) * 128 + r0) * 512 + c0;
                size_t b1 = ((size_t)(z * 3 + bx) * 128 + r0 + 8) * 512 + c0;
                *reinterpret_cast<float2*>(&outBuf[b0]) =
                    make_float2(acc[mf][nf][0], acc[mf][nf][1]);
                *reinterpret_cast<float2*>(&outBuf[b1]) =
                    make_float2(acc[mf][nf][2], acc[mf][nf][3]);
            }
        }
    }
}

// ---------------- reduces for the tensor path ----------------
__global__ void logits_reduce_kernel(const float* __restrict__ lpart,
                                     float* __restrict__ logits,
                                     const int* __restrict__ list,
                                     const int* __restrict__ cntPtr) {
    int i = blockIdx.x * blockDim.x + threadIdx.x;
    if (i >= *cntPtr) return;
    float s = 0.f;
    #pragma unroll
    for (int nt = 0; nt < 4; nt++) s += lpart[nt * 4992 + i];
    logits[list[i]] = s;
}

__global__ void tlinear_reduce_kernel(const float* __restrict__ part,
                                      const float* __restrict__ lb,
                                      float* __restrict__ hout,
                                      const int* __restrict__ list,
                                      const int* __restrict__ cntPtr) {
    int pos = blockIdx.x;
    if (pos >= *cntPtr) return;
    int node = list[pos];
    int mt = pos >> 7, row = pos & 127;
    for (int col = threadIdx.x; col < 512; col += blockDim.x) {
        float s = lb[col];
        #pragma unroll
        for (int z = 0; z < 8; z++)
            s += part[((size_t)(z * 3 + mt) * 128 + row) * 512 + col];
        hout[(size_t)node * 512 + col] = fmaxf(s, 0.f);
    }
}

// ---------------- SIMT GEMMs for small layers (proven round-3 code) ----------------
template <int CPT>
__device__ __forceinline__ void loadW(const float* __restrict__ w, size_t d,
                                      int dh, int col0, bool wact, float* out) {
    if (CPT == 2) {
        float2 t = wact ? *reinterpret_cast<const float2*>(&w[d * dh + col0])
                        : make_float2(0.f, 0.f);
        out[0] = t.x; out[1] = t.y;
    } else {
        out[0] = wact ? w[d * dh + col0] : 0.f;
    }
}

template <int ROWS, int CPT>
__global__ __launch_bounds__(256)
void gemm_logits_kernel(const float* __restrict__ hin,
                        const float* __restrict__ aw,
                        const float* __restrict__ aq,
                        float* __restrict__ logits,
                        const int* __restrict__ list,
                        const int* __restrict__ cntPtr,
                        int din, int dh) {
    const int tid = threadIdx.x;
    const int cnt = *cntPtr;
    const int row0 = blockIdx.x * ROWS;
    if (row0 >= cnt) return;
    const int rows = min(ROWS, cnt - row0);

    __shared__ int snode[ROWS];
    __shared__ ulonglong2 xs[ROWS / 4][33];
    if (tid < ROWS) snode[tid] = list[row0 + (tid < rows ? tid : 0)];
    __syncthreads();

    const int r = tid >> 3, q = tid & 7;
    const bool ract = (r < ROWS);
    const int col0 = CPT * tid;
    const bool wact = (col0 + CPT - 1 < dh);

    unsigned long long acc[ROWS / 2][CPT];
    #pragma unroll
    for (int rp = 0; rp < ROWS / 2; rp++)
        #pragma unroll
        for (int c = 0; c < CPT; c++) acc[rp][c] = 0ull;

    float4 v = make_float4(0.f, 0.f, 0.f, 0.f);
    size_t rowBase = 0;
    if (ract) {
        rowBase = (size_t)snode[r] * din;
        v = *reinterpret_cast<const float4*>(&hin[rowBase + q * 4]);
    }

    for (int d0 = 0; d0 < din; d0 += 32) {
        if (ract) {
            float* dst = (float*)&xs[r >> 2][q * 4];
            dst[0 * 4 + (r & 3)] = v.x;
            dst[1 * 4 + (r & 3)] = v.y;
            dst[2 * 4 + (r & 3)] = v.z;
            dst[3 * 4 + (r & 3)] = v.w;
        }
        __syncthreads();
        if (ract && d0 + 32 < din)
            v = *reinterpret_cast<const float4*>(&hin[rowBase + d0 + 32 + q * 4]);

        float wr[4][CPT];
        #pragma unroll
        for (int p = 0; p < 4; p++)
            loadW<CPT>(aw, (size_t)(d0 + p), dh, col0, wact, wr[p]);

        #pragma unroll
        for (int dd = 0; dd < 32; dd++) {
            unsigned long long w2[CPT];
            #pragma unroll
            for (int c = 0; c < CPT; c++) w2[c] = pack_dup(wr[dd & 3][c]);
            if (dd + 4 < 32)
                loadW<CPT>(aw, (size_t)(d0 + dd + 4), dh, col0, wact, wr[dd & 3]);
            #pragma unroll
            for (int g2 = 0; g2 < ROWS / 4; g2++) {
                ulonglong2 p = xs[g2][dd];
                #pragma unroll
                for (int c = 0; c < CPT; c++) {
                    fma2(acc[2 * g2 + 0][c], p.x, w2[c]);
                    fma2(acc[2 * g2 + 1][c], p.y, w2[c]);
                }
            }
        }
        __syncthreads();
    }

    float aqv[CPT];
    #pragma unroll
    for (int c = 0; c < CPT; c++)
        aqv[c] = (col0 + c < dh) ? aq[col0 + c] : 0.f;

    __shared__ float red[8][ROWS];
    const int lane = tid & 31, wd = tid >> 5;
    #pragma unroll
    for (int rr = 0; rr < ROWS; rr++) {
        int rp = rr >> 1;
        float s = 0.f;
        #pragma unroll
        for (int c = 0; c < CPT; c++) {
            unsigned long long a = acc[rp][c];
            unsigned u = (rr & 1) ? (unsigned)(a >> 32) : (unsigned)a;
            s += aqv[c] * fmaxf(__uint_as_float(u), 0.f);
        }
        #pragma unroll
        for (int off = 16; off > 0; off >>= 1)
            s += __shfl_xor_sync(0xffffffffu, s, off);
        if (lane == 0) red[wd][rr] = s;
    }
    __syncthreads();
    if (tid < rows) {
        float s = 0.f;
        #pragma unroll
        for (int w2 = 0; w2 < 8; w2++) s += red[w2][tid];
        logits[snode[tid]] = s;
    }
}

template <int ROWS, int CPT>
__global__ __launch_bounds__(256)
void gemm_linear_kernel(const float* __restrict__ hin,
                        const float* __restrict__ hN,
                        const float* __restrict__ lw,
                        float* __restrict__ part,
                        const int* __restrict__ list,
                        const int* __restrict__ cntPtr,
                        int din, int dh, int kch) {
    const int tid = threadIdx.x;
    const int cnt = *cntPtr;
    const int row0 = blockIdx.x * ROWS;
    if (row0 >= cnt) return;
    const int rows = min(ROWS, cnt - row0);
    const int z = blockIdx.z;
    const int k0 = z * kch, k1 = k0 + kch;

    __shared__ int snode[ROWS];
    __shared__ ulonglong2 xs[ROWS / 4][33];
    if (tid < ROWS) snode[tid] = list[row0 + (tid < rows ? tid : 0)];
    __syncthreads();

    const int r = tid >> 3, q = tid & 7;
    const bool ract = (r < ROWS);
    const int col0 = CPT * tid;
    const bool wact = (col0 + CPT - 1 < dh);

    unsigned long long acc[ROWS / 2][CPT];
    #pragma unroll
    for (int rp = 0; rp < ROWS / 2; rp++)
        #pragma unroll
        for (int c = 0; c < CPT; c++) acc[rp][c] = 0ull;

    size_t rowBase = 0, hnBase = 0;
    if (ract) {
        rowBase = (size_t)snode[r] * din;
        hnBase = (size_t)(row0 + (r < rows ? r : 0)) * din;
    }
    auto loadX = [&](int d) -> float4 {
        if (d < din) return *reinterpret_cast<const float4*>(&hin[rowBase + d]);
        return *reinterpret_cast<const float4*>(&hN[hnBase + (d - din)]);
    };

    float4 v = make_float4(0.f, 0.f, 0.f, 0.f);
    if (ract) v = loadX(k0 + q * 4);

    for (int d0 = k0; d0 < k1; d0 += 32) {
        if (ract) {
            float* dst = (float*)&xs[r >> 2][q * 4];
            dst[0 * 4 + (r & 3)] = v.x;
            dst[1 * 4 + (r & 3)] = v.y;
            dst[2 * 4 + (r & 3)] = v.z;
            dst[3 * 4 + (r & 3)] = v.w;
        }
        __syncthreads();
        if (ract && d0 + 32 < k1) v = loadX(d0 + 32 + q * 4);

        float wr[4][CPT];
        #pragma unroll
        for (int p = 0; p < 4; p++)
            loadW<CPT>(lw, (size_t)(d0 + p), dh, col0, wact, wr[p]);

        #pragma unroll
        for (int dd = 0; dd < 32; dd++) {
            unsigned long long w2[CPT];
            #pragma unroll
            for (int c = 0; c < CPT; c++) w2[c] = pack_dup(wr[dd & 3][c]);
            if (dd + 4 < 32)
                loadW<CPT>(lw, (size_t)(d0 + dd + 4), dh, col0, wact, wr[dd & 3]);
            #pragma unroll
            for (int g2 = 0; g2 < ROWS / 4; g2++) {
                ulonglong2 p = xs[g2][dd];
                #pragma unroll
                for (int c = 0; c < CPT; c++) {
                    fma2(acc[2 * g2 + 0][c], p.x, w2[c]);
                    fma2(acc[2 * g2 + 1][c], p.y, w2[c]);
                }
            }
        }
        __syncthreads();
    }

    if (wact) {
        #pragma unroll
        for (int rp = 0; rp < ROWS / 2; rp++) {
            int rA = 2 * rp, rB = 2 * rp + 1;
            #pragma unroll
            for (int c = 0; c < CPT; c++) {
                float lo = __uint_as_float((unsigned)acc[rp][c]);
                float hi = __uint_as_float((unsigned)(acc[rp][c] >> 32));
                if (rA < rows) part[((size_t)z * 320 + row0 + rA) * 512 + col0 + c] = lo;
                if (rB < rows) part[((size_t)z * 320 + row0 + rB) * 512 + col0 + c] = hi;
            }
        }
    }
}

__global__ void linear_reduce_kernel(const float* __restrict__ part,
                                     const float* __restrict__ lb,
                                     float* __restrict__ hout,
                                     const int* __restrict__ list,
                                     const int* __restrict__ cntPtr,
                                     int dh, int nz) {
    int pos = blockIdx.x;
    if (pos >= *cntPtr) return;
    int node = list[pos];
    for (int col = threadIdx.x; col < dh; col += blockDim.x) {
        float s = lb[col];
        for (int z = 0; z < nz; z++)
            s += part[((size_t)z * 320 + pos) * 512 + col];
        hout[(size_t)node * dh + col] = fmaxf(s, 0.f);
    }
}

// ---------------- softmax over 16 neighbors + weighted message ----------------
__global__ void attn_kernel(const float* __restrict__ hin,
                            const float* __restrict__ logits,
                            const int* __restrict__ senders,
                            const int* __restrict__ list,
                            const int* __restrict__ cntPtr,
                            float* __restrict__ hN, int din) {
    int pos = blockIdx.x;
    if (pos >= *cntPtr) return;
    int node = list[pos];
    int tid = threadIdx.x;

    __shared__ int   ss[16];
    __shared__ float sw[16];
    __shared__ float sinv;
    if (tid < 32) {
        float el = -1e30f;
        int s = 0;
        if (tid < 16) { s = senders[node * DEG + tid]; el = logits[s]; ss[tid] = s; }
        float m = el;
        #pragma unroll
        for (int off = 8; off > 0; off >>= 1) m = fmaxf(m, __shfl_xor_sync(0xffffffffu, m, off));
        float w = (tid < 16) ? expf(el - m) : 0.f;
        float sum = w;
        #pragma unroll
        for (int off = 8; off > 0; off >>= 1) sum += __shfl_xor_sync(0xffffffffu, sum, off);
        if (tid < 16) sw[tid] = w;
        if (tid == 0) sinv = 1.f / sum;
    }
    __syncthreads();
    float inv = sinv;
    int nd4 = din >> 2;
    for (int d4 = tid; d4 < nd4; d4 += blockDim.x) {
        float4 m = make_float4(0.f, 0.f, 0.f, 0.f);
        #pragma unroll
        for (int k = 0; k < 16; k++) {
            float4 x = *reinterpret_cast<const float4*>(&hin[(size_t)ss[k] * din + d4 * 4]);
            float wk = sw[k];
            m.x = fmaf(wk, x.x, m.x);
            m.y = fmaf(wk, x.y, m.y);
            m.z = fmaf(wk, x.z, m.z);
            m.w = fmaf(wk, x.w, m.w);
        }
        m.x *= inv; m.y *= inv; m.z *= inv; m.w *= inv;
        *reinterpret_cast<float4*>(&hN[(size_t)pos * din + d4 * 4]) = m;
    }
}

// ---------------- final: out = h3[14] @ ow + ob ----------------
__global__ void out_kernel(const float* __restrict__ ow,
                           const float* __restrict__ ob,
                           float* __restrict__ out) {
    __shared__ float hs[128];
    int tid = threadIdx.x;
    hs[tid] = g_h3[(size_t)14 * 128 + tid];
    __syncthreads();
    float acc = ob[tid];
    #pragma unroll 8
    for (int d = 0; d < 128; d++) acc = fmaf(hs[d], ow[d * 128 + tid], acc);
    out[tid] = acc;
}

// ---------------- launch ----------------
extern "C" void kernel_launch(void* const* d_in, const int* in_sizes, int n_in,
                              void* d_out, int out_size) {
    const float* X       = (const float*)d_in[0];
    const int*   senders = (const int*)d_in[1];
    const float* lw0 = (const float*)d_in[3];
    const float* lb0 = (const float*)d_in[4];
    const float* aw0 = (const float*)d_in[5];
    const float* aq0 = (const float*)d_in[6];
    const float* lw1 = (const float*)d_in[7];
    const float* lb1 = (const float*)d_in[8];
    const float* aw1 = (const float*)d_in[9];
    const float* aq1 = (const float*)d_in[10];
    const float* lw2 = (const float*)d_in[11];
    const float* lb2 = (const float*)d_in[12];
    const float* aw2 = (const float*)d_in[13];
    const float* aq2 = (const float*)d_in[14];
    const float* ow  = (const float*)d_in[15];
    const float* ob  = (const float*)d_in[16];

    int *l0, *l1, *l2, *l3, *cnt;
    float *logits, *hN, *part, *lpart, *partT, *wt0, *wtL, *h1, *h2, *h3;
    cudaGetSymbolAddress((void**)&l0, g_list0);
    cudaGetSymbolAddress((void**)&l1, g_list1);
    cudaGetSymbolAddress((void**)&l2, g_list2);
    cudaGetSymbolAddress((void**)&l3, g_list3);
    cudaGetSymbolAddress((void**)&cnt, g_cnt);
    cudaGetSymbolAddress((void**)&logits, g_logits);
    cudaGetSymbolAddress((void**)&hN, g_hN);
    cudaGetSymbolAddress((void**)&part, g_part);
    cudaGetSymbolAddress((void**)&lpart, g_lpart);
    cudaGetSymbolAddress((void**)&partT, g_partT);
    cudaGetSymbolAddress((void**)&wt0, g_wt0);
    cudaGetSymbolAddress((void**)&wtL, g_wtL);
    cudaGetSymbolAddress((void**)&h1, g_h1);
    cudaGetSymbolAddress((void**)&h2, g_h2);
    cudaGetSymbolAddress((void**)&h3, g_h3);

    clear_kernel<<<(NN + 255) / 256, 256>>>();
    cone_kernel<<<1, 1024>>>(senders);
    transpose_kernel<<<dim3(32, 16), dim3(32, 8)>>>(aw0, wt0, 1024, 512);
    transpose_kernel<<<dim3(64, 16), dim3(32, 8)>>>(lw0, wtL, 2048, 512);

    // ---- layer 0: tf32 mma.sync GEMMs ----
    mma_gemm_kernel<0><<<dim3(39, 4, 1), 256>>>(
        X, nullptr, wt0, aq0, lpart, l0, cnt + 0, 1024, 1024);
    logits_reduce_kernel<<<20, 256>>>(lpart, logits, l0, cnt + 0);
    attn_kernel<<<289, 256>>>(X, logits, senders, l1, cnt + 1, hN, 1024);
    mma_gemm_kernel<1><<<dim3(3, 4, 8), 256>>>(
        X, hN, wtL, nullptr, partT, l1, cnt + 1, 2048, 256);
    tlinear_reduce_kernel<<<289, 256>>>(partT, lb0, h1, l1, cnt + 1);

    // ---- layer 1: din=512, dh=256 (SIMT) ----
    gemm_logits_kernel<16, 1><<<19, 256>>>(h1, aw1, aq1, logits, l1, cnt + 1, 512, 256);
    attn_kernel<<<17, 256>>>(h1, logits, senders, l2, cnt + 2, hN, 512);
    gemm_linear_kernel<16, 1><<<dim3(2, 1, 4), 256>>>(h1, hN, lw1, part, l2, cnt + 2, 512, 256, 256);
    linear_reduce_kernel<<<17, 256>>>(part, lb1, h2, l2, cnt + 2, 256, 4);

    // ---- layer 2: din=256, dh=128 (SIMT) ----
    gemm_logits_kernel<16, 1><<<2, 256>>>(h2, aw2, aq2, logits, l2, cnt + 2, 256, 128);
    attn_kernel<<<1, 256>>>(h2, logits, senders, l3, cnt + 3, hN, 256);
    gemm_linear_kernel<16, 1><<<dim3(1, 1, 2), 256>>>(h2, hN, lw2, part, l3, cnt + 3, 256, 128, 256);
    linear_reduce_kernel<<<1, 128>>>(part, lb2, h3, l3, cnt + 3, 128, 2);

    out_kernel<<<1, 128>>>(ow, ob, (float*)d_out);
}

// round 8
// speedup vs baseline: 3.9148x; 1.0506x over previous
#include <cuda_runtime.h>
#include <cstdint>
#include <cstddef>

#define NN 20000
#define DEG 16

// ---------------- scratch (static device globals; no allocation) ----------------
__device__ int   g_mask0[NN];
__device__ int   g_mask1[NN];
__device__ int   g_mask2[NN];
__device__ int   g_list0[4928];
__device__ int   g_list1[320];
__device__ int   g_list2[32];
__device__ int   g_list3[1] = {14};
__device__ int   g_cnt[4] = {0, 0, 0, 1};
__device__ float g_logits[NN];
__device__ float g_hN[320 * 1024];
__device__ float g_part[8 * 320 * 512];        // SIMT split-K partials (layer 2)
__device__ float g_lpart[4 * 4992];            // logits per-Ntile partials
__device__ float g_partT[8 * 3 * 128 * 512];   // mma linear split-K partials
__device__ float g_wt0[512 * 1024];            // aw0^T [dh][din]
__device__ float g_wtL[512 * 2048];            // lw0^T [dh][2*din]
__device__ float g_wt1[256 * 512];             // aw1^T
__device__ float g_wtL1[256 * 1024];           // lw1^T
__device__ float g_h1[(size_t)NN * 512];
__device__ float g_h2[(size_t)NN * 256];
__device__ float g_h3[(size_t)NN * 128];

// ---------------- helpers ----------------
__device__ __forceinline__ uint32_t f2tf32(float f) {
    uint32_t r;
    asm("cvt.rna.tf32.f32 %0, %1;" : "=r"(r) : "f"(f));
    return r;
}
__device__ __forceinline__ void mma16x8x8(float* d, const uint32_t* a, const uint32_t* b) {
    asm volatile(
        "mma.sync.aligned.m16n8k8.row.col.f32.tf32.tf32.f32 "
        "{%0,%1,%2,%3}, {%4,%5,%6,%7}, {%8,%9}, {%0,%1,%2,%3};"
        : "+f"(d[0]), "+f"(d[1]), "+f"(d[2]), "+f"(d[3])
        : "r"(a[0]), "r"(a[1]), "r"(a[2]), "r"(a[3]), "r"(b[0]), "r"(b[1]));
}
__device__ __forceinline__ unsigned long long pack_dup(float w) {
    unsigned long long r;
    asm("mov.b64 %0, {%1, %1};" : "=l"(r) : "r"(__float_as_uint(w)));
    return r;
}
__device__ __forceinline__ void fma2(unsigned long long& acc,
                                     unsigned long long a, unsigned long long b) {
    asm("fma.rn.f32x2 %0, %1, %2, %0;" : "+l"(acc) : "l"(a), "l"(b));
}

// ---------------- cone construction ----------------
__global__ void clear_kernel() {
    int i = blockIdx.x * blockDim.x + threadIdx.x;
    if (i < NN) { g_mask0[i] = 0; g_mask1[i] = 0; g_mask2[i] = 0; }
    if (i < 3) g_cnt[i] = 0;
}

__global__ void cone_kernel(const int* __restrict__ senders) {
    const int tid = threadIdx.x;
    const int B = blockDim.x;
    if (tid < 17) {
        int s = (tid < 16) ? senders[14 * DEG + tid] : 14;
        if (atomicExch(&g_mask2[s], 1) == 0) g_list2[atomicAdd(&g_cnt[2], 1)] = s;
    }
    __syncthreads();
    int c2 = g_cnt[2];
    for (int t = tid; t < c2 * 17; t += B) {
        int i = t / 17, k = t - i * 17;
        int node = g_list2[i];
        int s = (k < 16) ? senders[node * DEG + k] : node;
        if (atomicExch(&g_mask1[s], 1) == 0) g_list1[atomicAdd(&g_cnt[1], 1)] = s;
    }
    __syncthreads();
    int c1 = g_cnt[1];
    for (int t = tid; t < c1 * 17; t += B) {
        int i = t / 17, k = t - i * 17;
        int node = g_list1[i];
        int s = (k < 16) ? senders[node * DEG + k] : node;
        if (atomicExch(&g_mask0[s], 1) == 0) g_list0[atomicAdd(&g_cnt[0], 1)] = s;
    }
}

// ---------------- merged weight transposes: dst[n][k] = src[k][n] ----------------
__global__ void transpose_all_kernel(const float* __restrict__ aw0,
                                     const float* __restrict__ lw0,
                                     const float* __restrict__ aw1,
                                     const float* __restrict__ lw1) {
    const float* src; float* dst; int K, N;
    switch (blockIdx.z) {
        case 0:  src = aw0; dst = g_wt0;  K = 1024; N = 512; break;
        case 1:  src = lw0; dst = g_wtL;  K = 2048; N = 512; break;
        case 2:  src = aw1; dst = g_wt1;  K = 512;  N = 256; break;
        default: src = lw1; dst = g_wtL1; K = 1024; N = 256; break;
    }
    int k0 = blockIdx.x * 32, n0 = blockIdx.y * 32;
    if (k0 >= K || n0 >= N) return;
    __shared__ float t[32][33];
    int x = threadIdx.x, y = threadIdx.y;
    #pragma unroll
    for (int j = 0; j < 32; j += 8)
        t[y + j][x] = src[(size_t)(k0 + y + j) * N + n0 + x];
    __syncthreads();
    #pragma unroll
    for (int j = 0; j < 32; j += 8)
        dst[(size_t)(n0 + y + j) * K + k0 + x] = t[x][y + j];
}

// ---------------- mma.sync tf32 GEMM (generalized) ----------------
// Tile: M=128, N=128, K-chunk=32. 256 threads = 8 warps, warp tile 32x64.
// MODE 0 (logits): A = gather(h, list), B = wt; epilogue -> aq.relu partial
//                  per N-tile into lpart[ntile*4992 + m0+row].
// MODE 1 (linear): A = concat(h[list], hN); raw D partials into
//                  partT[((z*MT+bx)*128+r)*DH + n0+c].
#define ASTR 36

template <int MODE>
__global__ __launch_bounds__(256, 1)
void mma_gemm_kernel(const float* __restrict__ X,
                     const float* __restrict__ hN,
                     const float* __restrict__ wt,
                     const float* __restrict__ aq,
                     float* __restrict__ outBuf,
                     const int* __restrict__ list,
                     const int* __restrict__ cntPtr,
                     int din, int Ktot, int kPerSplit, int MT, int DH) {
    __shared__ uint32_t As[128 * ASTR];
    __shared__ uint32_t Bs[128 * ASTR];
    __shared__ int snode[128];
    __shared__ float sred[128];
    __shared__ float saq[128];

    const int tid = threadIdx.x;
    const int w = tid >> 5, lane = tid & 31;
    const int g = lane >> 2, t4 = lane & 3;
    const int wm = w >> 1, wn = w & 1;
    const int cnt = *cntPtr;
    const int m0 = blockIdx.x * 128;
    if (m0 >= cnt) return;
    const int n0 = blockIdx.y * 128;
    const int kBase = blockIdx.z * kPerSplit;
    const int nch = kPerSplit / 32;

    if (tid < 128) {
        int p = m0 + tid; if (p >= cnt) p = cnt - 1;
        snode[tid] = list[p];
        if (MODE == 0) saq[tid] = aq[n0 + tid];
    }
    __syncthreads();

    float acc[2][8][4];
    #pragma unroll
    for (int mf = 0; mf < 2; mf++)
        #pragma unroll
        for (int nf = 0; nf < 8; nf++)
            #pragma unroll
            for (int e = 0; e < 4; e++) acc[mf][nf][e] = 0.f;

    float4 ra[4], rb[4];
    auto loadChunk = [&](int c) {
        const int k0 = kBase + c * 32;
        #pragma unroll
        for (int j = 0; j < 4; j++) {
            int i = j * 256 + tid;
            int row = i >> 3, col = (i & 7) * 4;
            const float* srcA;
            if (MODE == 0) {
                srcA = X + (size_t)snode[row] * din + k0 + col;
            } else {
                int d = k0 + col;
                if (d < din) srcA = X + (size_t)snode[row] * din + d;
                else {
                    int p = m0 + row; if (p >= cnt) p = cnt - 1;
                    srcA = hN + (size_t)p * din + (d - din);
                }
            }
            ra[j] = *reinterpret_cast<const float4*>(srcA);
            rb[j] = *reinterpret_cast<const float4*>(
                wt + (size_t)(n0 + row) * Ktot + k0 + col);
        }
    };
    auto stageChunk = [&]() {
        #pragma unroll
        for (int j = 0; j < 4; j++) {
            int i = j * 256 + tid;
            int row = i >> 3, col = (i & 7) * 4;
            uint4 va = make_uint4(f2tf32(ra[j].x), f2tf32(ra[j].y),
                                  f2tf32(ra[j].z), f2tf32(ra[j].w));
            uint4 vb = make_uint4(f2tf32(rb[j].x), f2tf32(rb[j].y),
                                  f2tf32(rb[j].z), f2tf32(rb[j].w));
            *reinterpret_cast<uint4*>(&As[row * ASTR + col]) = va;
            *reinterpret_cast<uint4*>(&Bs[row * ASTR + col]) = vb;
        }
    };

    loadChunk(0);
    for (int c = 0; c < nch; c++) {
        stageChunk();
        __syncthreads();
        if (c + 1 < nch) loadChunk(c + 1);

        #pragma unroll
        for (int ks = 0; ks < 4; ks++) {
            const int k0 = ks * 8;
            uint32_t af[2][4];
            #pragma unroll
            for (int mf = 0; mf < 2; mf++) {
                int r = wm * 32 + mf * 16 + g;
                af[mf][0] = As[r * ASTR + k0 + t4];
                af[mf][1] = As[(r + 8) * ASTR + k0 + t4];
                af[mf][2] = As[r * ASTR + k0 + t4 + 4];
                af[mf][3] = As[(r + 8) * ASTR + k0 + t4 + 4];
            }
            #pragma unroll
            for (int nf = 0; nf < 8; nf++) {
                int cN = wn * 64 + nf * 8 + g;
                uint32_t bf[2];
                bf[0] = Bs[cN * ASTR + k0 + t4];
                bf[1] = Bs[cN * ASTR + k0 + t4 + 4];
                mma16x8x8(acc[0][nf], af[0], bf);
                mma16x8x8(acc[1][nf], af[1], bf);
            }
        }
        __syncthreads();
    }

    if (MODE == 0) {
        float s[2][2] = {{0.f, 0.f}, {0.f, 0.f}};
        #pragma unroll
        for (int mf = 0; mf < 2; mf++)
            #pragma unroll
            for (int nf = 0; nf < 8; nf++) {
                int c0 = wn * 64 + nf * 8 + t4 * 2;
                float a0 = saq[c0], a1 = saq[c0 + 1];
                s[mf][0] += a0 * fmaxf(acc[mf][nf][0], 0.f) + a1 * fmaxf(acc[mf][nf][1], 0.f);
                s[mf][1] += a0 * fmaxf(acc[mf][nf][2], 0.f) + a1 * fmaxf(acc[mf][nf][3], 0.f);
            }
        #pragma unroll
        for (int mf = 0; mf < 2; mf++)
            #pragma unroll
            for (int h = 0; h < 2; h++) {
                s[mf][h] += __shfl_xor_sync(0xffffffffu, s[mf][h], 1);
                s[mf][h] += __shfl_xor_sync(0xffffffffu, s[mf][h], 2);
            }
        if (wn == 0 && t4 == 0) {
            #pragma unroll
            for (int mf = 0; mf < 2; mf++) {
                sred[wm * 32 + mf * 16 + g] = s[mf][0];
                sred[wm * 32 + mf * 16 + g + 8] = s[mf][1];
            }
        }
        __syncthreads();
        if (wn == 1 && t4 == 0) {
            #pragma unroll
            for (int mf = 0; mf < 2; mf++) {
                sred[wm * 32 + mf * 16 + g] += s[mf][0];
                sred[wm * 32 + mf * 16 + g + 8] += s[mf][1];
            }
        }
        __syncthreads();
        if (tid < 128)
            outBuf[blockIdx.y * 4992 + m0 + tid] = sred[tid];
    } else {
        const int bx = blockIdx.x, z = blockIdx.z;
        #pragma unroll
        for (int mf = 0; mf < 2; mf++) {
            int r0 = wm * 32 + mf * 16 + g;
            #pragma unroll
            for (int nf = 0; nf < 8; nf++) {
                int c0 = n0 + wn * 64 + nf * 8 + t4 * 2;
                size_t b0 = ((size_t)(z * MT + bx) * 128 + r0) * DH + c0;
                size_t b1 = ((size_t)(z * MT + bx) * 128 + r0 + 8) * DH + c0;
                *reinterpret_cast<float2*>(&outBuf[b0]) =
                    make_float2(acc[mf][nf][0], acc[mf][nf][1]);
                *reinterpret_cast<float2*>(&outBuf[b1]) =
                    make_float2(acc[mf][nf][2], acc[mf][nf][3]);
            }
        }
    }
}

// ---------------- reduces for the tensor path ----------------
__global__ void logits_reduce_kernel(const float* __restrict__ lpart,
                                     float* __restrict__ logits,
                                     const int* __restrict__ list,
                                     const int* __restrict__ cntPtr,
                                     int nt) {
    int i = blockIdx.x * blockDim.x + threadIdx.x;
    if (i >= *cntPtr) return;
    float s = 0.f;
    for (int n = 0; n < nt; n++) s += lpart[n * 4992 + i];
    logits[list[i]] = s;
}

__global__ void tlinear_reduce_kernel(const float* __restrict__ part,
                                      const float* __restrict__ lb,
                                      float* __restrict__ hout,
                                      const int* __restrict__ list,
                                      const int* __restrict__ cntPtr,
                                      int nz, int MT, int DH) {
    int pos = blockIdx.x;
    if (pos >= *cntPtr) return;
    int node = list[pos];
    int mt = pos >> 7, row = pos & 127;
    for (int col = threadIdx.x; col < DH; col += blockDim.x) {
        float s = lb[col];
        for (int z = 0; z < nz; z++)
            s += part[((size_t)(z * MT + mt) * 128 + row) * DH + col];
        hout[(size_t)node * DH + col] = fmaxf(s, 0.f);
    }
}

// ---------------- SIMT GEMMs (layer 2 only) ----------------
template <int ROWS, int CPT>
__global__ __launch_bounds__(256)
void gemm_logits_kernel(const float* __restrict__ hin,
                        const float* __restrict__ aw,
                        const float* __restrict__ aq,
                        float* __restrict__ logits,
                        const int* __restrict__ list,
                        const int* __restrict__ cntPtr,
                        int din, int dh) {
    const int tid = threadIdx.x;
    const int cnt = *cntPtr;
    const int row0 = blockIdx.x * ROWS;
    if (row0 >= cnt) return;
    const int rows = min(ROWS, cnt - row0);

    __shared__ int snode[ROWS];
    __shared__ ulonglong2 xs[ROWS / 4][33];
    if (tid < ROWS) snode[tid] = list[row0 + (tid < rows ? tid : 0)];
    __syncthreads();

    const int r = tid >> 3, q = tid & 7;
    const bool ract = (r < ROWS);
    const int col0 = CPT * tid;
    const bool wact = (col0 + CPT - 1 < dh);

    unsigned long long acc[ROWS / 2][CPT];
    #pragma unroll
    for (int rp = 0; rp < ROWS / 2; rp++)
        #pragma unroll
        for (int c = 0; c < CPT; c++) acc[rp][c] = 0ull;

    float4 v = make_float4(0.f, 0.f, 0.f, 0.f);
    size_t rowBase = 0;
    if (ract) {
        rowBase = (size_t)snode[r] * din;
        v = *reinterpret_cast<const float4*>(&hin[rowBase + q * 4]);
    }

    for (int d0 = 0; d0 < din; d0 += 32) {
        if (ract) {
            float* dst = (float*)&xs[r >> 2][q * 4];
            dst[0 * 4 + (r & 3)] = v.x;
            dst[1 * 4 + (r & 3)] = v.y;
            dst[2 * 4 + (r & 3)] = v.z;
            dst[3 * 4 + (r & 3)] = v.w;
        }
        __syncthreads();
        if (ract && d0 + 32 < din)
            v = *reinterpret_cast<const float4*>(&hin[rowBase + d0 + 32 + q * 4]);

        float wr[4];
        #pragma unroll
        for (int p = 0; p < 4; p++)
            wr[p] = wact ? aw[(size_t)(d0 + p) * dh + col0] : 0.f;

        #pragma unroll
        for (int dd = 0; dd < 32; dd++) {
            unsigned long long w2 = pack_dup(wr[dd & 3]);
            if (dd + 4 < 32)
                wr[dd & 3] = wact ? aw[(size_t)(d0 + dd + 4) * dh + col0] : 0.f;
            #pragma unroll
            for (int g2 = 0; g2 < ROWS / 4; g2++) {
                ulonglong2 p = xs[g2][dd];
                fma2(acc[2 * g2 + 0][0], p.x, w2);
                fma2(acc[2 * g2 + 1][0], p.y, w2);
            }
        }
        __syncthreads();
    }

    float aqv = (col0 < dh) ? aq[col0] : 0.f;
    __shared__ float red[8][ROWS];
    const int lane = tid & 31, wd = tid >> 5;
    #pragma unroll
    for (int rr = 0; rr < ROWS; rr++) {
        int rp = rr >> 1;
        unsigned long long a = acc[rp][0];
        unsigned u = (rr & 1) ? (unsigned)(a >> 32) : (unsigned)a;
        float s = aqv * fmaxf(__uint_as_float(u), 0.f);
        #pragma unroll
        for (int off = 16; off > 0; off >>= 1)
            s += __shfl_xor_sync(0xffffffffu, s, off);
        if (lane == 0) red[wd][rr] = s;
    }
    __syncthreads();
    if (tid < rows) {
        float s = 0.f;
        #pragma unroll
        for (int w2 = 0; w2 < 8; w2++) s += red[w2][tid];
        logits[snode[tid]] = s;
    }
}

template <int ROWS, int CPT>
__global__ __launch_bounds__(256)
void gemm_linear_kernel(const float* __restrict__ hin,
                        const float* __restrict__ hN,
                        const float* __restrict__ lw,
                        float* __restrict__ part,
                        const int* __restrict__ list,
                        const int* __restrict__ cntPtr,
                        int din, int dh, int kch) {
    const int tid = threadIdx.x;
    const int cnt = *cntPtr;
    const int row0 = blockIdx.x * ROWS;
    if (row0 >= cnt) return;
    const int rows = min(ROWS, cnt - row0);
    const int z = blockIdx.z;
    const int k0 = z * kch, k1 = k0 + kch;

    __shared__ int snode[ROWS];
    __shared__ ulonglong2 xs[ROWS / 4][33];
    if (tid < ROWS) snode[tid] = list[row0 + (tid < rows ? tid : 0)];
    __syncthreads();

    const int r = tid >> 3, q = tid & 7;
    const bool ract = (r < ROWS);
    const int col0 = CPT * tid;
    const bool wact = (col0 + CPT - 1 < dh);

    unsigned long long acc[ROWS / 2];
    #pragma unroll
    for (int rp = 0; rp < ROWS / 2; rp++) acc[rp] = 0ull;

    size_t rowBase = 0, hnBase = 0;
    if (ract) {
        rowBase = (size_t)snode[r] * din;
        hnBase = (size_t)(row0 + (r < rows ? r : 0)) * din;
    }
    auto loadX = [&](int d) -> float4 {
        if (d < din) return *reinterpret_cast<const float4*>(&hin[rowBase + d]);
        return *reinterpret_cast<const float4*>(&hN[hnBase + (d - din)]);
    };

    float4 v = make_float4(0.f, 0.f, 0.f, 0.f);
    if (ract) v = loadX(k0 + q * 4);

    for (int d0 = k0; d0 < k1; d0 += 32) {
        if (ract) {
            float* dst = (float*)&xs[r >> 2][q * 4];
            dst[0 * 4 + (r & 3)] = v.x;
            dst[1 * 4 + (r & 3)] = v.y;
            dst[2 * 4 + (r & 3)] = v.z;
            dst[3 * 4 + (r & 3)] = v.w;
        }
        __syncthreads();
        if (ract && d0 + 32 < k1) v = loadX(d0 + 32 + q * 4);

        float wr[4];
        #pragma unroll
        for (int p = 0; p < 4; p++)
            wr[p] = wact ? lw[(size_t)(d0 + p) * dh + col0] : 0.f;

        #pragma unroll
        for (int dd = 0; dd < 32; dd++) {
            unsigned long long w2 = pack_dup(wr[dd & 3]);
            if (dd + 4 < 32)
                wr[dd & 3] = wact ? lw[(size_t)(d0 + dd + 4) * dh + col0] : 0.f;
            #pragma unroll
            for (int g2 = 0; g2 < ROWS / 4; g2++) {
                ulonglong2 p = xs[g2][dd];
                fma2(acc[2 * g2 + 0], p.x, w2);
                fma2(acc[2 * g2 + 1], p.y, w2);
            }
        }
        __syncthreads();
    }

    if (wact) {
        #pragma unroll
        for (int rp = 0; rp < ROWS / 2; rp++) {
            int rA = 2 * rp, rB = 2 * rp + 1;
            float lo = __uint_as_float((unsigned)acc[rp]);
            float hi = __uint_as_float((unsigned)(acc[rp] >> 32));
            if (rA < rows) part[((size_t)z * 320 + row0 + rA) * 512 + col0] = lo;
            if (rB < rows) part[((size_t)z * 320 + row0 + rB) * 512 + col0] = hi;
        }
    }
}

__global__ void linear_reduce_kernel(const float* __restrict__ part,
                                     const float* __restrict__ lb,
                                     float* __restrict__ hout,
                                     const int* __restrict__ list,
                                     const int* __restrict__ cntPtr,
                                     int dh, int nz) {
    int pos = blockIdx.x;
    if (pos >= *cntPtr) return;
    int node = list[pos];
    for (int col = threadIdx.x; col < dh; col += blockDim.x) {
        float s = lb[col];
        for (int z = 0; z < nz; z++)
            s += part[((size_t)z * 320 + pos) * 512 + col];
        hout[(size_t)node * dh + col] = fmaxf(s, 0.f);
    }
}

// ---------------- softmax over 16 neighbors + weighted message ----------------
// grid.y splits the feature range for parallelism.
__global__ void attn_kernel(const float* __restrict__ hin,
                            const float* __restrict__ logits,
                            const int* __restrict__ senders,
                            const int* __restrict__ list,
                            const int* __restrict__ cntPtr,
                            float* __restrict__ hN, int din) {
    int pos = blockIdx.x;
    if (pos >= *cntPtr) return;
    int node = list[pos];
    int tid = threadIdx.x;

    __shared__ int   ss[16];
    __shared__ float sw[16];
    __shared__ float sinv;
    if (tid < 32) {
        float el = -1e30f;
        int s = 0;
        if (tid < 16) { s = senders[node * DEG + tid]; el = logits[s]; ss[tid] = s; }
        float m = el;
        #pragma unroll
        for (int off = 8; off > 0; off >>= 1) m = fmaxf(m, __shfl_xor_sync(0xffffffffu, m, off));
        float w = (tid < 16) ? expf(el - m) : 0.f;
        float sum = w;
        #pragma unroll
        for (int off = 8; off > 0; off >>= 1) sum += __shfl_xor_sync(0xffffffffu, sum, off);
        if (tid < 16) sw[tid] = w;
        if (tid == 0) sinv = 1.f / sum;
    }
    __syncthreads();
    float inv = sinv;
    int nd4 = din >> 2;
    int stride = blockDim.x * gridDim.y;
    for (int d4 = blockIdx.y * blockDim.x + tid; d4 < nd4; d4 += stride) {
        float4 m = make_float4(0.f, 0.f, 0.f, 0.f);
        #pragma unroll
        for (int k = 0; k < 16; k++) {
            float4 x = *reinterpret_cast<const float4*>(&hin[(size_t)ss[k] * din + d4 * 4]);
            float wk = sw[k];
            m.x = fmaf(wk, x.x, m.x);
            m.y = fmaf(wk, x.y, m.y);
            m.z = fmaf(wk, x.z, m.z);
            m.w = fmaf(wk, x.w, m.w);
        }
        m.x *= inv; m.y *= inv; m.z *= inv; m.w *= inv;
        *reinterpret_cast<float4*>(&hN[(size_t)pos * din + d4 * 4]) = m;
    }
}

// ---------------- final: out = h3[14] @ ow + ob ----------------
__global__ void out_kernel(const float* __restrict__ ow,
                           const float* __restrict__ ob,
                           float* __restrict__ out) {
    __shared__ float hs[128];
    int tid = threadIdx.x;
    hs[tid] = g_h3[(size_t)14 * 128 + tid];
    __syncthreads();
    float acc = ob[tid];
    #pragma unroll 8
    for (int d = 0; d < 128; d++) acc = fmaf(hs[d], ow[d * 128 + tid], acc);
    out[tid] = acc;
}

// ---------------- launch ----------------
extern "C" void kernel_launch(void* const* d_in, const int* in_sizes, int n_in,
                              void* d_out, int out_size) {
    const float* X       = (const float*)d_in[0];
    const int*   senders = (const int*)d_in[1];
    const float* lw0 = (const float*)d_in[3];
    const float* lb0 = (const float*)d_in[4];
    const float* aw0 = (const float*)d_in[5];
    const float* aq0 = (const float*)d_in[6];
    const float* lw1 = (const float*)d_in[7];
    const float* lb1 = (const float*)d_in[8];
    const float* aw1 = (const float*)d_in[9];
    const float* aq1 = (const float*)d_in[10];
    const float* lw2 = (const float*)d_in[11];
    const float* lb2 = (const float*)d_in[12];
    const float* aw2 = (const float*)d_in[13];
    const float* aq2 = (const float*)d_in[14];
    const float* ow  = (const float*)d_in[15];
    const float* ob  = (const float*)d_in[16];

    int *l0, *l1, *l2, *l3, *cnt;
    float *logits, *hN, *part, *lpart, *partT, *wt0, *wtL, *wt1, *wtL1, *h1, *h2, *h3;
    cudaGetSymbolAddress((void**)&l0, g_list0);
    cudaGetSymbolAddress((void**)&l1, g_list1);
    cudaGetSymbolAddress((void**)&l2, g_list2);
    cudaGetSymbolAddress((void**)&l3, g_list3);
    cudaGetSymbolAddress((void**)&cnt, g_cnt);
    cudaGetSymbolAddress((void**)&logits, g_logits);
    cudaGetSymbolAddress((void**)&hN, g_hN);
    cudaGetSymbolAddress((void**)&part, g_part);
    cudaGetSymbolAddress((void**)&lpart, g_lpart);
    cudaGetSymbolAddress((void**)&partT, g_partT);
    cudaGetSymbolAddress((void**)&wt0, g_wt0);
    cudaGetSymbolAddress((void**)&wtL, g_wtL);
    cudaGetSymbolAddress((void**)&wt1, g_wt1);
    cudaGetSymbolAddress((void**)&wtL1, g_wtL1);
    cudaGetSymbolAddress((void**)&h1, g_h1);
    cudaGetSymbolAddress((void**)&h2, g_h2);
    cudaGetSymbolAddress((void**)&h3, g_h3);

    clear_kernel<<<(NN + 255) / 256, 256>>>();
    cone_kernel<<<1, 1024>>>(senders);
    transpose_all_kernel<<<dim3(64, 16, 4), dim3(32, 8)>>>(aw0, lw0, aw1, lw1);

    // ---- layer 0: tf32 mma.sync (din=1024, dh=512) ----
    mma_gemm_kernel<0><<<dim3(39, 4, 1), 256>>>(
        X, nullptr, wt0, aq0, lpart, l0, cnt + 0, 1024, 1024, 1024, 0, 0);
    logits_reduce_kernel<<<20, 256>>>(lpart, logits, l0, cnt + 0, 4);
    attn_kernel<<<dim3(289, 2), 256>>>(X, logits, senders, l1, cnt + 1, hN, 1024);
    mma_gemm_kernel<1><<<dim3(3, 4, 8), 256>>>(
        X, hN, wtL, nullptr, partT, l1, cnt + 1, 1024, 2048, 256, 3, 512);
    tlinear_reduce_kernel<<<289, 256>>>(partT, lb0, h1, l1, cnt + 1, 8, 3, 512);

    // ---- layer 1: tf32 mma.sync (din=512, dh=256) ----
    mma_gemm_kernel<0><<<dim3(3, 2, 1), 256>>>(
        h1, nullptr, wt1, aq1, lpart, l1, cnt + 1, 512, 512, 512, 0, 0);
    logits_reduce_kernel<<<2, 256>>>(lpart, logits, l1, cnt + 1, 2);
    attn_kernel<<<dim3(17, 1), 256>>>(h1, logits, senders, l2, cnt + 2, hN, 512);
    mma_gemm_kernel<1><<<dim3(1, 2, 2), 256>>>(
        h1, hN, wtL1, nullptr, partT, l2, cnt + 2, 512, 1024, 512, 1, 256);
    tlinear_reduce_kernel<<<17, 256>>>(partT, lb1, h2, l2, cnt + 2, 2, 1, 256);

    // ---- layer 2: din=256, dh=128 (SIMT) ----
    gemm_logits_kernel<16, 1><<<2, 256>>>(h2, aw2, aq2, logits, l2, cnt + 2, 256, 128);
    attn_kernel<<<dim3(1, 1), 256>>>(h2, logits, senders, l3, cnt + 3, hN, 256);
    gemm_linear_kernel<16, 1><<<dim3(1, 1, 2), 256>>>(h2, hN, lw2, part, l3, cnt + 3, 256, 128, 256);
    linear_reduce_kernel<<<1, 128>>>(part, lb2, h3, l3, cnt + 3, 128, 2);

    out_kernel<<<1, 128>>>(ow, ob, (float*)d_out);
}